// round 1
// baseline (speedup 1.0000x reference)
#include <cuda_runtime.h>
#include <cuda_bf16.h>
#include <stdint.h>

#define BATCH 2
#define SEQ   2048
#define DMODEL 2048
#define NHEAD 16
#define HDIM  128
#define HID   5888
#define TOK   (BATCH*SEQ)            // 4096
#define CH    ((size_t)TOK*DMODEL)   // 8388608 floats
#define EPSV  1e-5f
#define SCALE_ATT 0.08838834764831845f   // 1/sqrt(128)

// ---------------- scratch (static device memory: allocation-guard safe) -----
// layout: nq, nk, nv, fx, q, k, v, y, h  (9 * CH)  then ffn1 (TOK*HID)
__device__ float g_scr[9*CH + (size_t)TOK*HID];

// ---------------- helpers ---------------------------------------------------
__device__ __forceinline__ uint32_t f2tf32(float x) {
    uint32_t r;
    asm("cvt.rna.tf32.f32 %0, %1;" : "=r"(r) : "f"(x));
    return r;
}

__device__ __forceinline__ void mma_tf32(float (&c)[4], const uint32_t (&a)[4],
                                         const uint32_t (&b)[2]) {
    asm volatile(
        "mma.sync.aligned.m16n8k8.row.col.f32.tf32.tf32.f32 "
        "{%0,%1,%2,%3}, {%4,%5,%6,%7}, {%8,%9}, {%0,%1,%2,%3};\n"
        : "+f"(c[0]), "+f"(c[1]), "+f"(c[2]), "+f"(c[3])
        : "r"(a[0]), "r"(a[1]), "r"(a[2]), "r"(a[3]), "r"(b[0]), "r"(b[1]));
}

// ---------------- layernorm -------------------------------------------------
__global__ __launch_bounds__(256) void layernorm_kernel(
    const float* __restrict__ x, const float* __restrict__ w,
    const float* __restrict__ b, float* __restrict__ out)
{
    const int row = blockIdx.x;
    const int t = threadIdx.x;
    const float4* xp = (const float4*)(x + (size_t)row * DMODEL);
    float4 v0 = xp[t], v1 = xp[t + 256];
    float s  = v0.x + v0.y + v0.z + v0.w + v1.x + v1.y + v1.z + v1.w;
    float ss = v0.x*v0.x + v0.y*v0.y + v0.z*v0.z + v0.w*v0.w
             + v1.x*v1.x + v1.y*v1.y + v1.z*v1.z + v1.w*v1.w;
    __shared__ float sred[16];
    const int lane = t & 31, warp = t >> 5;
#pragma unroll
    for (int o = 16; o; o >>= 1) {
        s  += __shfl_xor_sync(0xffffffffu, s,  o);
        ss += __shfl_xor_sync(0xffffffffu, ss, o);
    }
    if (lane == 0) { sred[warp] = s; sred[8 + warp] = ss; }
    __syncthreads();
    if (t < 32) {
        s  = (t < 8) ? sred[t]     : 0.f;
        ss = (t < 8) ? sred[8 + t] : 0.f;
#pragma unroll
        for (int o = 4; o; o >>= 1) {
            s  += __shfl_xor_sync(0xffffffffu, s,  o);
            ss += __shfl_xor_sync(0xffffffffu, ss, o);
        }
        if (t == 0) { sred[0] = s; sred[1] = ss; }
    }
    __syncthreads();
    const float mean = sred[0] * (1.f / DMODEL);
    const float var  = sred[1] * (1.f / DMODEL) - mean * mean;
    const float inv  = rsqrtf(var + EPSV);
    const float4* wp = (const float4*)w;
    const float4* bp = (const float4*)b;
    float4 w0 = wp[t], w1 = wp[t + 256], b0 = bp[t], b1 = bp[t + 256];
    float4 o0, o1;
    o0.x = (v0.x - mean) * inv * w0.x + b0.x;
    o0.y = (v0.y - mean) * inv * w0.y + b0.y;
    o0.z = (v0.z - mean) * inv * w0.z + b0.z;
    o0.w = (v0.w - mean) * inv * w0.w + b0.w;
    o1.x = (v1.x - mean) * inv * w1.x + b1.x;
    o1.y = (v1.y - mean) * inv * w1.y + b1.y;
    o1.z = (v1.z - mean) * inv * w1.z + b1.z;
    o1.w = (v1.w - mean) * inv * w1.w + b1.w;
    float4* op = (float4*)(out + (size_t)row * DMODEL);
    op[t] = o0;
    op[t + 256] = o1;
}

// ---------------- generic tf32 NT GEMM: C[M,N] = A[M,K] @ Bw[N,K]^T ---------
#define ACT_NONE 0
#define ACT_GELU 1

template <int ACT, bool RES>
__global__ __launch_bounds__(256) void gemm_tf32_kernel(
    const float* __restrict__ A, const float* __restrict__ Bw,
    const float* __restrict__ bias, const float* __restrict__ Resid,
    float* __restrict__ C, int M, int N, int K)
{
    __shared__ uint32_t As[2][128 * 20];
    __shared__ uint32_t Bs[2][128 * 20];
    const int t = threadIdx.x;
    const int warp = t >> 5, lane = t & 31;
    const int wm = (warp & 1) << 6;    // 2 warps in m : 0, 64
    const int wn = (warp >> 1) << 5;   // 4 warps in n : 0,32,64,96
    const int g = lane >> 2, tg = lane & 3;

    const float* Ap = A  + (size_t)(blockIdx.y * 128) * K;
    const float* Bp = Bw + (size_t)(blockIdx.x * 128) * K;

    const int id0 = t * 2, id1 = t * 2 + 1;
    const int lr0 = id0 >> 2, lc0 = (id0 & 3) << 2;
    const int lr1 = id1 >> 2, lc1 = (id1 & 3) << 2;

    float4 ra0, ra1, rb0, rb1;
    ra0 = *(const float4*)(Ap + (size_t)lr0 * K + lc0);
    ra1 = *(const float4*)(Ap + (size_t)lr1 * K + lc1);
    rb0 = *(const float4*)(Bp + (size_t)lr0 * K + lc0);
    rb1 = *(const float4*)(Bp + (size_t)lr1 * K + lc1);

#define ST4(dst, base, v)                     \
    dst[(base) + 0] = f2tf32((v).x);          \
    dst[(base) + 1] = f2tf32((v).y);          \
    dst[(base) + 2] = f2tf32((v).z);          \
    dst[(base) + 3] = f2tf32((v).w);

    ST4(As[0], lr0 * 20 + lc0, ra0)
    ST4(As[0], lr1 * 20 + lc1, ra1)
    ST4(Bs[0], lr0 * 20 + lc0, rb0)
    ST4(Bs[0], lr1 * 20 + lc1, rb1)
    __syncthreads();

    float acc[4][4][4];
#pragma unroll
    for (int i = 0; i < 4; i++)
#pragma unroll
        for (int j = 0; j < 4; j++)
#pragma unroll
            for (int r = 0; r < 4; r++) acc[i][j][r] = 0.f;

    const int nK = K >> 4;
    int buf = 0;
    for (int kt = 0; kt < nK; kt++) {
        if (kt + 1 < nK) {
            const int k0 = (kt + 1) << 4;
            ra0 = *(const float4*)(Ap + (size_t)lr0 * K + k0 + lc0);
            ra1 = *(const float4*)(Ap + (size_t)lr1 * K + k0 + lc1);
            rb0 = *(const float4*)(Bp + (size_t)lr0 * K + k0 + lc0);
            rb1 = *(const float4*)(Bp + (size_t)lr1 * K + k0 + lc1);
        }
#pragma unroll
        for (int kk = 0; kk < 16; kk += 8) {
            uint32_t af[4][4], bf[4][2];
#pragma unroll
            for (int i = 0; i < 4; i++) {
                const int r0 = wm + i * 16 + g;
                af[i][0] = As[buf][r0 * 20 + kk + tg];
                af[i][1] = As[buf][(r0 + 8) * 20 + kk + tg];
                af[i][2] = As[buf][r0 * 20 + kk + tg + 4];
                af[i][3] = As[buf][(r0 + 8) * 20 + kk + tg + 4];
            }
#pragma unroll
            for (int j = 0; j < 4; j++) {
                const int c0 = wn + j * 8 + g;
                bf[j][0] = Bs[buf][c0 * 20 + kk + tg];
                bf[j][1] = Bs[buf][c0 * 20 + kk + tg + 4];
            }
#pragma unroll
            for (int i = 0; i < 4; i++)
#pragma unroll
                for (int j = 0; j < 4; j++)
                    mma_tf32(acc[i][j], af[i], bf[j]);
        }
        __syncthreads();
        if (kt + 1 < nK) {
            const int nb = buf ^ 1;
            ST4(As[nb], lr0 * 20 + lc0, ra0)
            ST4(As[nb], lr1 * 20 + lc1, ra1)
            ST4(Bs[nb], lr0 * 20 + lc0, rb0)
            ST4(Bs[nb], lr1 * 20 + lc1, rb1)
            __syncthreads();
        }
        buf ^= 1;
    }
#undef ST4

    const int rowb = blockIdx.y * 128 + wm;
    const int colb = blockIdx.x * 128 + wn;
#pragma unroll
    for (int i = 0; i < 4; i++) {
#pragma unroll
        for (int j = 0; j < 4; j++) {
            const int row0 = rowb + i * 16 + g;
            const int col0 = colb + j * 8 + tg * 2;
            const float bia0 = bias[col0], bia1 = bias[col0 + 1];
#pragma unroll
            for (int hr = 0; hr < 2; hr++) {
                const int row = row0 + hr * 8;
                float v0 = acc[i][j][hr * 2 + 0] + bia0;
                float v1 = acc[i][j][hr * 2 + 1] + bia1;
                if (RES) {
                    v0 += Resid[(size_t)row * N + col0];
                    v1 += Resid[(size_t)row * N + col0 + 1];
                }
                if (ACT == ACT_GELU) {
                    v0 = 0.5f * v0 * (1.f + erff(v0 * 0.7071067811865475f));
                    v1 = 0.5f * v1 * (1.f + erff(v1 * 0.7071067811865475f));
                }
                *(float2*)&C[(size_t)row * N + col0] = make_float2(v0, v1);
            }
        }
    }
}

// ---------------- per-head rmsnorm + rope (in-place) ------------------------
__global__ __launch_bounds__(256) void qknorm_rope_kernel(
    float* __restrict__ x, const float* __restrict__ w,
    const float* __restrict__ freqs)
{
    const int token = blockIdx.x;
    const int pos = token & (SEQ - 1);
    const int warp = threadIdx.x >> 5, lane = threadIdx.x & 31;
    __shared__ float rb[8][32];
    const float4 wv = ((const float4*)w)[lane];
#pragma unroll
    for (int hh = 0; hh < 2; hh++) {
        const int h = warp + hh * 8;
        float* p = x + (size_t)token * DMODEL + h * HDIM;
        float4 v = ((float4*)p)[lane];
        float ssq = v.x*v.x + v.y*v.y + v.z*v.z + v.w*v.w;
#pragma unroll
        for (int o = 16; o; o >>= 1) ssq += __shfl_xor_sync(0xffffffffu, ssq, o);
        const float inv = rsqrtf(ssq * (1.f / HDIM) + EPSV);
        float o0 = v.x * inv * wv.x, o1 = v.y * inv * wv.y;
        float o2 = v.z * inv * wv.z, o3 = v.w * inv * wv.w;
        const int d0 = lane * 4;
        if (d0 < 32) {
            rb[warp][d0] = o0; rb[warp][d0 + 1] = o1;
            rb[warp][d0 + 2] = o2; rb[warp][d0 + 3] = o3;
        }
        __syncwarp();
        if (d0 < 32) {
            float r[4];
#pragma unroll
            for (int i = 0; i < 4; i++) {
                const int d = d0 + i, ii = d >> 1;
                const float x1 = rb[warp][ii], x2 = rb[warp][ii + 16];
                const float c  = freqs[pos * 32 + ii * 2];
                const float sn = freqs[pos * 32 + ii * 2 + 1];
                r[i] = (d & 1) ? (x2 * c + x1 * sn) : (x1 * c - x2 * sn);
            }
            o0 = r[0]; o1 = r[1]; o2 = r[2]; o3 = r[3];
        }
        __syncwarp();
        ((float4*)p)[lane] = make_float4(o0, o1, o2, o3);
    }
}

// ---------------- causal flash attention (fp32) -----------------------------
__global__ __launch_bounds__(256) void attn_kernel(
    const float* __restrict__ Q, const float* __restrict__ Kx,
    const float* __restrict__ Vx, float* __restrict__ O)
{
    __shared__ float Ks[32][144];    // col map: pc = d + 4*(d>>5) -> bank-spread
    __shared__ float Vs[32][144];
    const int qb = blockIdx.x, bh = blockIdx.y;
    const int b = bh >> 4, h = bh & 15;
    const size_t base = ((size_t)b * SEQ) * DMODEL + h * HDIM;
    const int t = threadIdx.x;
    const int r = t >> 2, cg = t & 3;
    const int qrow = qb * 64 + r;

    float qreg[32];
    {
        const float* qp = Q + base + (size_t)qrow * DMODEL + cg * 32;
#pragma unroll
        for (int i = 0; i < 8; i++) {
            float4 v4 = ((const float4*)qp)[i];
            qreg[4*i] = v4.x; qreg[4*i+1] = v4.y; qreg[4*i+2] = v4.z; qreg[4*i+3] = v4.w;
        }
    }
    float m = -1e30f, l = 0.f;
    float acc[32];
#pragma unroll
    for (int i = 0; i < 32; i++) acc[i] = 0.f;

    const int jr = t >> 3, q8 = t & 7;
    const int nkt = (qb * 64 + 64) >> 5;
    for (int kt = 0; kt < nkt; kt++) {
        const int kv0 = kt << 5;
        __syncthreads();
        {
            const float* kp = Kx + base + (size_t)(kv0 + jr) * DMODEL;
            const float* vp = Vx + base + (size_t)(kv0 + jr) * DMODEL;
#pragma unroll
            for (int i = 0; i < 4; i++) {
                const int d = (q8 + 8 * i) * 4;
                const int pc = d + ((d >> 5) << 2);
                *(float4*)&Ks[jr][pc] = *(const float4*)(kp + d);
                *(float4*)&Vs[jr][pc] = *(const float4*)(vp + d);
            }
        }
        __syncthreads();
        float sc[32];
#pragma unroll
        for (int j = 0; j < 32; j++) {
            const float4* kr = (const float4*)&Ks[j][cg * 36];
            float p = 0.f;
#pragma unroll
            for (int d4 = 0; d4 < 8; d4++) {
                float4 kv = kr[d4];
                p += qreg[4*d4] * kv.x + qreg[4*d4+1] * kv.y
                   + qreg[4*d4+2] * kv.z + qreg[4*d4+3] * kv.w;
            }
            p += __shfl_xor_sync(0xffffffffu, p, 1);
            p += __shfl_xor_sync(0xffffffffu, p, 2);
            p *= SCALE_ATT;
            if (kv0 + j > qrow) p = -65504.f;
            sc[j] = p;
        }
        float mx = m;
#pragma unroll
        for (int j = 0; j < 32; j++) mx = fmaxf(mx, sc[j]);
        const float corr = __expf(m - mx);
        l *= corr;
#pragma unroll
        for (int i = 0; i < 32; i++) acc[i] *= corr;
#pragma unroll
        for (int j = 0; j < 32; j++) {
            const float p = __expf(sc[j] - mx);
            l += p;
            const float4* vr = (const float4*)&Vs[j][cg * 36];
#pragma unroll
            for (int d4 = 0; d4 < 8; d4++) {
                float4 vv = vr[d4];
                acc[4*d4]   += p * vv.x;
                acc[4*d4+1] += p * vv.y;
                acc[4*d4+2] += p * vv.z;
                acc[4*d4+3] += p * vv.w;
            }
        }
        m = mx;
    }
    const float invl = 1.f / l;
    float* op = O + base + (size_t)qrow * DMODEL + cg * 32;
#pragma unroll
    for (int d4 = 0; d4 < 8; d4++) {
        ((float4*)op)[d4] = make_float4(acc[4*d4] * invl, acc[4*d4+1] * invl,
                                        acc[4*d4+2] * invl, acc[4*d4+3] * invl);
    }
}

// ---------------- launcher --------------------------------------------------
extern "C" void kernel_launch(void* const* d_in, const int* in_sizes, int n_in,
                              void* d_out, int out_size)
{
    const float* x0      = (const float*)d_in[0];
    const float* x1      = (const float*)d_in[1];
    const float* x2      = (const float*)d_in[2];
    const float* x3      = (const float*)d_in[3];
    const float* freqs   = (const float*)d_in[5];
    const float* wq_w    = (const float*)d_in[7];
    const float* wq_b    = (const float*)d_in[8];
    const float* wk_w    = (const float*)d_in[9];
    const float* wk_b    = (const float*)d_in[10];
    const float* wv_w    = (const float*)d_in[11];
    const float* wv_b    = (const float*)d_in[12];
    const float* wo_w    = (const float*)d_in[13];
    const float* wo_b    = (const float*)d_in[14];
    const float* qn_w    = (const float*)d_in[15];
    const float* kn_w    = (const float*)d_in[16];
    const float* ln0_w   = (const float*)d_in[17];
    const float* ln0_b   = (const float*)d_in[18];
    const float* ln1_w   = (const float*)d_in[19];
    const float* ln1_b   = (const float*)d_in[20];
    const float* ln2_w   = (const float*)d_in[21];
    const float* ln2_b   = (const float*)d_in[22];
    const float* ffn_w   = (const float*)d_in[23];
    const float* ffn_b   = (const float*)d_in[24];
    const float* w1_w    = (const float*)d_in[25];
    const float* w1_b    = (const float*)d_in[26];
    const float* w2_w    = (const float*)d_in[27];
    const float* w2_b    = (const float*)d_in[28];
    float* out = (float*)d_out;

    float* scr = nullptr;
    cudaGetSymbolAddress((void**)&scr, g_scr);
    float* nq   = scr + 0 * CH;
    float* nk   = scr + 1 * CH;
    float* nv   = scr + 2 * CH;
    float* fx   = scr + 3 * CH;
    float* q    = scr + 4 * CH;
    float* k    = scr + 5 * CH;
    float* v    = scr + 6 * CH;
    float* y    = scr + 7 * CH;
    float* hbuf = scr + 8 * CH;
    float* ffn1 = scr + 9 * CH;

    // 1. layernorms
    layernorm_kernel<<<TOK, 256>>>(x0, ln0_w, ln0_b, nq);
    layernorm_kernel<<<TOK, 256>>>(x1, ln1_w, ln1_b, nk);
    layernorm_kernel<<<TOK, 256>>>(x2, ln2_w, ln2_b, nv);
    layernorm_kernel<<<TOK, 256>>>(x3, ffn_w, ffn_b, fx);

    // 2. QKV projections
    dim3 gq(DMODEL / 128, TOK / 128);
    gemm_tf32_kernel<ACT_NONE, false><<<gq, 256>>>(nq, wq_w, wq_b, nullptr, q,
                                                   TOK, DMODEL, DMODEL);
    gemm_tf32_kernel<ACT_NONE, false><<<gq, 256>>>(nk, wk_w, wk_b, nullptr, k,
                                                   TOK, DMODEL, DMODEL);
    gemm_tf32_kernel<ACT_NONE, false><<<gq, 256>>>(nv, wv_w, wv_b, nullptr, v,
                                                   TOK, DMODEL, DMODEL);

    // 3. qk rmsnorm + rope
    qknorm_rope_kernel<<<TOK, 256>>>(q, qn_w, freqs);
    qknorm_rope_kernel<<<TOK, 256>>>(k, kn_w, freqs);

    // 4. causal attention
    attn_kernel<<<dim3(SEQ / 64, BATCH * NHEAD), 256>>>(q, k, v, y);

    // 5. o-projection + residual (h = x3 + y@wo^T + wo_b)
    gemm_tf32_kernel<ACT_NONE, true><<<gq, 256>>>(y, wo_w, wo_b, x3, hbuf,
                                                  TOK, DMODEL, DMODEL);

    // 6. ffn1 + exact gelu
    dim3 g1(HID / 128, TOK / 128);
    gemm_tf32_kernel<ACT_GELU, false><<<g1, 256>>>(fx, w1_w, w1_b, nullptr,
                                                   ffn1, TOK, HID, DMODEL);

    // 7. ffn2 + residual -> final output
    gemm_tf32_kernel<ACT_NONE, true><<<gq, 256>>>(ffn1, w2_w, w2_b, hbuf, out,
                                                  TOK, DMODEL, HID);
}

// round 3
// speedup vs baseline: 2.2211x; 2.2211x over previous
#include <cuda_runtime.h>
#include <cuda_bf16.h>
#include <stdint.h>

#define BATCH 2
#define SEQ   2048
#define DMODEL 2048
#define NHEAD 16
#define HDIM  128
#define HID   5888
#define TOK   (BATCH*SEQ)            // 4096
#define CH    ((size_t)TOK*DMODEL)   // 8388608 floats
#define EPSV  1e-5f
#define SCALE_ATT 0.08838834764831845f   // 1/sqrt(128)

#define WQKVO_SZ ((size_t)DMODEL*DMODEL)      // 4194304
#define W12_SZ   ((size_t)HID*DMODEL)         // 12058624

// scratch: 9 activation buffers + ffn1 + rounded weights
__device__ float g_scr[9*CH + (size_t)TOK*HID + 4*WQKVO_SZ + 2*W12_SZ];

// ---------------- helpers ---------------------------------------------------
__device__ __forceinline__ uint32_t smem_u32(const void* p) {
    uint32_t a;
    asm("{ .reg .u64 t; cvta.to.shared.u64 t, %1; cvt.u32.u64 %0, t; }"
        : "=r"(a) : "l"(p));
    return a;
}
__device__ __forceinline__ float f2tf32f(float x) {
    uint32_t r;
    asm("cvt.rna.tf32.f32 %0, %1;" : "=r"(r) : "f"(x));
    return __uint_as_float(r);
}
__device__ __forceinline__ void cpasync16(uint32_t dst, const void* src) {
    asm volatile("cp.async.cg.shared.global [%0], [%1], 16;" :: "r"(dst), "l"(src) : "memory");
}
#define CP_COMMIT() asm volatile("cp.async.commit_group;" ::: "memory")
#define CP_WAIT2()  asm volatile("cp.async.wait_group 2;" ::: "memory")

#define LDSM4(r, addr) \
    asm volatile("ldmatrix.sync.aligned.m8n8.x4.shared.b16 {%0,%1,%2,%3}, [%4];" \
        : "=r"((r)[0]), "=r"((r)[1]), "=r"((r)[2]), "=r"((r)[3]) : "r"(addr))

__device__ __forceinline__ void mma_tf32(float (&c)[4], const uint32_t (&a)[4],
                                         uint32_t b0, uint32_t b1) {
    asm volatile(
        "mma.sync.aligned.m16n8k8.row.col.f32.tf32.tf32.f32 "
        "{%0,%1,%2,%3}, {%4,%5,%6,%7}, {%8,%9}, {%0,%1,%2,%3};\n"
        : "+f"(c[0]), "+f"(c[1]), "+f"(c[2]), "+f"(c[3])
        : "r"(a[0]), "r"(a[1]), "r"(a[2]), "r"(a[3]), "r"(b0), "r"(b1));
}

// ---------------- tf32 rounding pass (weights) ------------------------------
__global__ __launch_bounds__(256) void round_tf32_kernel(
    const float4* __restrict__ in, float4* __restrict__ out, int n4)
{
    const int i = blockIdx.x * 256 + threadIdx.x;
    if (i < n4) {
        float4 v = in[i];
        v.x = f2tf32f(v.x); v.y = f2tf32f(v.y);
        v.z = f2tf32f(v.z); v.w = f2tf32f(v.w);
        out[i] = v;
    }
}

// ---------------- layernorm (output rounded to tf32) ------------------------
__global__ __launch_bounds__(256) void layernorm_kernel(
    const float* __restrict__ x, const float* __restrict__ w,
    const float* __restrict__ b, float* __restrict__ out)
{
    const int row = blockIdx.x;
    const int t = threadIdx.x;
    const float4* xp = (const float4*)(x + (size_t)row * DMODEL);
    float4 v0 = xp[t], v1 = xp[t + 256];
    float s  = v0.x + v0.y + v0.z + v0.w + v1.x + v1.y + v1.z + v1.w;
    float ss = v0.x*v0.x + v0.y*v0.y + v0.z*v0.z + v0.w*v0.w
             + v1.x*v1.x + v1.y*v1.y + v1.z*v1.z + v1.w*v1.w;
    __shared__ float sred[16];
    const int lane = t & 31, warp = t >> 5;
#pragma unroll
    for (int o = 16; o; o >>= 1) {
        s  += __shfl_xor_sync(0xffffffffu, s,  o);
        ss += __shfl_xor_sync(0xffffffffu, ss, o);
    }
    if (lane == 0) { sred[warp] = s; sred[8 + warp] = ss; }
    __syncthreads();
    if (t < 32) {
        s  = (t < 8) ? sred[t]     : 0.f;
        ss = (t < 8) ? sred[8 + t] : 0.f;
#pragma unroll
        for (int o = 4; o; o >>= 1) {
            s  += __shfl_xor_sync(0xffffffffu, s,  o);
            ss += __shfl_xor_sync(0xffffffffu, ss, o);
        }
        if (t == 0) { sred[0] = s; sred[1] = ss; }
    }
    __syncthreads();
    const float mean = sred[0] * (1.f / DMODEL);
    const float var  = sred[1] * (1.f / DMODEL) - mean * mean;
    const float inv  = rsqrtf(var + EPSV);
    const float4* wp = (const float4*)w;
    const float4* bp = (const float4*)b;
    float4 w0 = wp[t], w1 = wp[t + 256], b0 = bp[t], b1 = bp[t + 256];
    float4 o0, o1;
    o0.x = f2tf32f((v0.x - mean) * inv * w0.x + b0.x);
    o0.y = f2tf32f((v0.y - mean) * inv * w0.y + b0.y);
    o0.z = f2tf32f((v0.z - mean) * inv * w0.z + b0.z);
    o0.w = f2tf32f((v0.w - mean) * inv * w0.w + b0.w);
    o1.x = f2tf32f((v1.x - mean) * inv * w1.x + b1.x);
    o1.y = f2tf32f((v1.y - mean) * inv * w1.y + b1.y);
    o1.z = f2tf32f((v1.z - mean) * inv * w1.z + b1.z);
    o1.w = f2tf32f((v1.w - mean) * inv * w1.w + b1.w);
    float4* op = (float4*)(out + (size_t)row * DMODEL);
    op[t] = o0;
    op[t + 256] = o1;
}

// ------- pipelined tf32 mma GEMM: C[M,N] = A[M,K] @ Bw[N,K]^T ---------------
// inputs A, Bw must already be tf32-rounded. 128x128 tile, BK=32, 4 stages.
#define ACT_NONE 0
#define ACT_GELU 1
#define GSMEM (4 * 32768)      // 128 KB

template <int ACT, bool RES, bool ROUND>
__global__ __launch_bounds__(256, 1) void gemm_mma_kernel(
    const float* __restrict__ A, const float* __restrict__ Bw,
    const float* __restrict__ bias, const float* __restrict__ Resid,
    float* __restrict__ C, int M, int N, int K)
{
    extern __shared__ char smem[];
    const uint32_t s0 = smem_u32(smem);
    const int tid = threadIdx.x;
    const int warp = tid >> 5, lane = tid & 31;
    const int wm = (warp & 1) << 6;     // m offset: 0 / 64
    const int wn = (warp >> 1) << 5;    // n offset: 0,32,64,96
    const float* Abase = A  + (size_t)(blockIdx.y * 128) * K;
    const float* Bbase = Bw + (size_t)(blockIdx.x * 128) * K;
    const int nk = K >> 5;

    const int ldrow = (tid * 2) >> 4;       // not used; keep simple below
    (void)ldrow;

    // prologue: stages 0..2
#pragma unroll
    for (int s = 0; s < 3; ++s) {
        if (s < nk) {
            const uint32_t sA = s0 + s * 32768, sB = sA + 16384;
#pragma unroll
            for (int p = 0; p < 4; ++p) {
                const int cid = tid + (p << 8);
                const int row = cid >> 3, c4 = cid & 7;
                const uint32_t sw = row * 128 + ((c4 ^ (row & 7)) << 4);
                const size_t gof = (size_t)row * K + s * 32 + c4 * 4;
                cpasync16(sA + sw, Abase + gof);
                cpasync16(sB + sw, Bbase + gof);
            }
        }
        CP_COMMIT();
    }

    float acc[4][4][4];
#pragma unroll
    for (int i = 0; i < 4; i++)
#pragma unroll
        for (int j = 0; j < 4; j++)
#pragma unroll
            for (int r = 0; r < 4; r++) acc[i][j][r] = 0.f;

    const int mq = lane >> 3, l7 = lane & 7;

    for (int kt = 0; kt < nk; ++kt) {
        CP_WAIT2();
        __syncthreads();
        // issue loads for stage kt+3 (overwrites stage consumed at kt-1)
        if (kt + 3 < nk) {
            const int s = (kt + 3) & 3;
            const uint32_t sA = s0 + s * 32768, sB = sA + 16384;
#pragma unroll
            for (int p = 0; p < 4; ++p) {
                const int cid = tid + (p << 8);
                const int row = cid >> 3, c4 = cid & 7;
                const uint32_t sw = row * 128 + ((c4 ^ (row & 7)) << 4);
                const size_t gof = (size_t)row * K + (kt + 3) * 32 + c4 * 4;
                cpasync16(sA + sw, Abase + gof);
                cpasync16(sB + sw, Bbase + gof);
            }
        }
        CP_COMMIT();

        const uint32_t sA = s0 + (kt & 3) * 32768, sB = sA + 16384;
#pragma unroll
        for (int kk = 0; kk < 4; ++kk) {
            uint32_t af[4][4], bf[2][4];
#pragma unroll
            for (int i = 0; i < 4; ++i) {
                const int row = wm + i * 16 + ((mq & 1) << 3) + l7;
                const int ch = (kk << 1) + (mq >> 1);
                LDSM4(af[i], sA + row * 128 + ((ch ^ (row & 7)) << 4));
            }
#pragma unroll
            for (int jp = 0; jp < 2; ++jp) {
                const int row = wn + jp * 16 + ((mq >> 1) << 3) + l7;
                const int ch = (kk << 1) + (mq & 1);
                LDSM4(bf[jp], sB + row * 128 + ((ch ^ (row & 7)) << 4));
            }
#pragma unroll
            for (int i = 0; i < 4; ++i)
#pragma unroll
                for (int j = 0; j < 4; ++j)
                    mma_tf32(acc[i][j], af[i],
                             bf[j >> 1][(j & 1) << 1], bf[j >> 1][((j & 1) << 1) + 1]);
        }
    }

    // epilogue
    const int g = lane >> 2, tg = lane & 3;
    const int rowbase = blockIdx.y * 128 + wm;
    const int colbase = blockIdx.x * 128 + wn;
#pragma unroll
    for (int i = 0; i < 4; ++i) {
#pragma unroll
        for (int j = 0; j < 4; ++j) {
            const int r0 = rowbase + i * 16 + g;
            const int c0 = colbase + j * 8 + tg * 2;
            const float bia0 = bias[c0], bia1 = bias[c0 + 1];
#pragma unroll
            for (int hr = 0; hr < 2; ++hr) {
                const int row = r0 + hr * 8;
                float v0 = acc[i][j][hr * 2 + 0] + bia0;
                float v1 = acc[i][j][hr * 2 + 1] + bia1;
                if (RES) {
                    v0 += Resid[(size_t)row * N + c0];
                    v1 += Resid[(size_t)row * N + c0 + 1];
                }
                if (ACT == ACT_GELU) {
                    v0 = 0.5f * v0 * (1.f + erff(v0 * 0.7071067811865475f));
                    v1 = 0.5f * v1 * (1.f + erff(v1 * 0.7071067811865475f));
                }
                if (ROUND) { v0 = f2tf32f(v0); v1 = f2tf32f(v1); }
                *(float2*)&C[(size_t)row * N + c0] = make_float2(v0, v1);
            }
        }
    }
}

// ---------------- per-head rmsnorm + rope (in-place) ------------------------
__global__ __launch_bounds__(256) void qknorm_rope_kernel(
    float* __restrict__ x, const float* __restrict__ w,
    const float* __restrict__ freqs)
{
    const int token = blockIdx.x;
    const int pos = token & (SEQ - 1);
    const int warp = threadIdx.x >> 5, lane = threadIdx.x & 31;
    __shared__ float rb[8][32];
    const float4 wv = ((const float4*)w)[lane];
#pragma unroll
    for (int hh = 0; hh < 2; hh++) {
        const int h = warp + hh * 8;
        float* p = x + (size_t)token * DMODEL + h * HDIM;
        float4 v = ((float4*)p)[lane];
        float ssq = v.x*v.x + v.y*v.y + v.z*v.z + v.w*v.w;
#pragma unroll
        for (int o = 16; o; o >>= 1) ssq += __shfl_xor_sync(0xffffffffu, ssq, o);
        const float inv = rsqrtf(ssq * (1.f / HDIM) + EPSV);
        float o0 = v.x * inv * wv.x, o1 = v.y * inv * wv.y;
        float o2 = v.z * inv * wv.z, o3 = v.w * inv * wv.w;
        const int d0 = lane * 4;
        if (d0 < 32) {
            rb[warp][d0] = o0; rb[warp][d0 + 1] = o1;
            rb[warp][d0 + 2] = o2; rb[warp][d0 + 3] = o3;
        }
        __syncwarp();
        if (d0 < 32) {
            float r[4];
#pragma unroll
            for (int i = 0; i < 4; i++) {
                const int d = d0 + i, ii = d >> 1;
                const float x1 = rb[warp][ii], x2 = rb[warp][ii + 16];
                const float c  = freqs[pos * 32 + ii * 2];
                const float sn = freqs[pos * 32 + ii * 2 + 1];
                r[i] = (d & 1) ? (x2 * c + x1 * sn) : (x1 * c - x2 * sn);
            }
            o0 = r[0]; o1 = r[1]; o2 = r[2]; o3 = r[3];
        }
        __syncwarp();
        ((float4*)p)[lane] = make_float4(o0, o1, o2, o3);
    }
}

// ---------------- causal flash attention (fp32, out rounded to tf32) --------
__global__ __launch_bounds__(256) void attn_kernel(
    const float* __restrict__ Q, const float* __restrict__ Kx,
    const float* __restrict__ Vx, float* __restrict__ O)
{
    __shared__ float Ks[32][144];
    __shared__ float Vs[32][144];
    const int qb = blockIdx.x, bh = blockIdx.y;
    const int b = bh >> 4, h = bh & 15;
    const size_t base = ((size_t)b * SEQ) * DMODEL + h * HDIM;
    const int t = threadIdx.x;
    const int r = t >> 2, cg = t & 3;
    const int qrow = qb * 64 + r;

    float qreg[32];
    {
        const float* qp = Q + base + (size_t)qrow * DMODEL + cg * 32;
#pragma unroll
        for (int i = 0; i < 8; i++) {
            float4 v4 = ((const float4*)qp)[i];
            qreg[4*i] = v4.x; qreg[4*i+1] = v4.y; qreg[4*i+2] = v4.z; qreg[4*i+3] = v4.w;
        }
    }
    float m = -1e30f, l = 0.f;
    float acc[32];
#pragma unroll
    for (int i = 0; i < 32; i++) acc[i] = 0.f;

    const int jr = t >> 3, q8 = t & 7;
    const int nkt = (qb * 64 + 64) >> 5;
    for (int kt = 0; kt < nkt; kt++) {
        const int kv0 = kt << 5;
        __syncthreads();
        {
            const float* kp = Kx + base + (size_t)(kv0 + jr) * DMODEL;
            const float* vp = Vx + base + (size_t)(kv0 + jr) * DMODEL;
#pragma unroll
            for (int i = 0; i < 4; i++) {
                const int d = (q8 + 8 * i) * 4;
                const int pc = d + ((d >> 5) << 2);
                *(float4*)&Ks[jr][pc] = *(const float4*)(kp + d);
                *(float4*)&Vs[jr][pc] = *(const float4*)(vp + d);
            }
        }
        __syncthreads();
        float sc[32];
#pragma unroll
        for (int j = 0; j < 32; j++) {
            const float4* kr = (const float4*)&Ks[j][cg * 36];
            float p = 0.f;
#pragma unroll
            for (int d4 = 0; d4 < 8; d4++) {
                float4 kv = kr[d4];
                p += qreg[4*d4] * kv.x + qreg[4*d4+1] * kv.y
                   + qreg[4*d4+2] * kv.z + qreg[4*d4+3] * kv.w;
            }
            p += __shfl_xor_sync(0xffffffffu, p, 1);
            p += __shfl_xor_sync(0xffffffffu, p, 2);
            p *= SCALE_ATT;
            if (kv0 + j > qrow) p = -65504.f;
            sc[j] = p;
        }
        float mx = m;
#pragma unroll
        for (int j = 0; j < 32; j++) mx = fmaxf(mx, sc[j]);
        const float corr = __expf(m - mx);
        l *= corr;
#pragma unroll
        for (int i = 0; i < 32; i++) acc[i] *= corr;
#pragma unroll
        for (int j = 0; j < 32; j++) {
            const float p = __expf(sc[j] - mx);
            l += p;
            const float4* vr = (const float4*)&Vs[j][cg * 36];
#pragma unroll
            for (int d4 = 0; d4 < 8; d4++) {
                float4 vv = vr[d4];
                acc[4*d4]   += p * vv.x;
                acc[4*d4+1] += p * vv.y;
                acc[4*d4+2] += p * vv.z;
                acc[4*d4+3] += p * vv.w;
            }
        }
        m = mx;
    }
    const float invl = 1.f / l;
    float* op = O + base + (size_t)qrow * DMODEL + cg * 32;
#pragma unroll
    for (int d4 = 0; d4 < 8; d4++) {
        ((float4*)op)[d4] = make_float4(
            f2tf32f(acc[4*d4] * invl),   f2tf32f(acc[4*d4+1] * invl),
            f2tf32f(acc[4*d4+2] * invl), f2tf32f(acc[4*d4+3] * invl));
    }
}

// ---------------- launcher --------------------------------------------------
extern "C" void kernel_launch(void* const* d_in, const int* in_sizes, int n_in,
                              void* d_out, int out_size)
{
    const float* x0      = (const float*)d_in[0];
    const float* x1      = (const float*)d_in[1];
    const float* x2      = (const float*)d_in[2];
    const float* x3      = (const float*)d_in[3];
    const float* freqs   = (const float*)d_in[5];
    const float* wq_w    = (const float*)d_in[7];
    const float* wq_b    = (const float*)d_in[8];
    const float* wk_w    = (const float*)d_in[9];
    const float* wk_b    = (const float*)d_in[10];
    const float* wv_w    = (const float*)d_in[11];
    const float* wv_b    = (const float*)d_in[12];
    const float* wo_w    = (const float*)d_in[13];
    const float* wo_b    = (const float*)d_in[14];
    const float* qn_w    = (const float*)d_in[15];
    const float* kn_w    = (const float*)d_in[16];
    const float* ln0_w   = (const float*)d_in[17];
    const float* ln0_b   = (const float*)d_in[18];
    const float* ln1_w   = (const float*)d_in[19];
    const float* ln1_b   = (const float*)d_in[20];
    const float* ln2_w   = (const float*)d_in[21];
    const float* ln2_b   = (const float*)d_in[22];
    const float* ffn_w   = (const float*)d_in[23];
    const float* ffn_b   = (const float*)d_in[24];
    const float* w1_w    = (const float*)d_in[25];
    const float* w1_b    = (const float*)d_in[26];
    const float* w2_w    = (const float*)d_in[27];
    const float* w2_b    = (const float*)d_in[28];
    float* out = (float*)d_out;

    float* scr = nullptr;
    cudaGetSymbolAddress((void**)&scr, g_scr);
    float* nq   = scr + 0 * CH;
    float* nk   = scr + 1 * CH;
    float* nv   = scr + 2 * CH;
    float* fx   = scr + 3 * CH;
    float* q    = scr + 4 * CH;
    float* k    = scr + 5 * CH;
    float* v    = scr + 6 * CH;
    float* y    = scr + 7 * CH;
    float* hbuf = scr + 8 * CH;
    float* ffn1 = scr + 9 * CH;
    float* wr   = ffn1 + (size_t)TOK * HID;
    float* wq_r = wr;
    float* wk_r = wq_r + WQKVO_SZ;
    float* wv_r = wk_r + WQKVO_SZ;
    float* wo_r = wv_r + WQKVO_SZ;
    float* w1_r = wo_r + WQKVO_SZ;
    float* w2_r = w1_r + W12_SZ;

    cudaFuncSetAttribute(gemm_mma_kernel<ACT_NONE, false, false>,
                         cudaFuncAttributeMaxDynamicSharedMemorySize, GSMEM);
    cudaFuncSetAttribute(gemm_mma_kernel<ACT_NONE, true, false>,
                         cudaFuncAttributeMaxDynamicSharedMemorySize, GSMEM);
    cudaFuncSetAttribute(gemm_mma_kernel<ACT_GELU, false, true>,
                         cudaFuncAttributeMaxDynamicSharedMemorySize, GSMEM);

    // 0. round weights to tf32
    const int nw4 = (int)(WQKVO_SZ / 4), nh4 = (int)(W12_SZ / 4);
    round_tf32_kernel<<<(nw4 + 255) / 256, 256>>>((const float4*)wq_w, (float4*)wq_r, nw4);
    round_tf32_kernel<<<(nw4 + 255) / 256, 256>>>((const float4*)wk_w, (float4*)wk_r, nw4);
    round_tf32_kernel<<<(nw4 + 255) / 256, 256>>>((const float4*)wv_w, (float4*)wv_r, nw4);
    round_tf32_kernel<<<(nw4 + 255) / 256, 256>>>((const float4*)wo_w, (float4*)wo_r, nw4);
    round_tf32_kernel<<<(nh4 + 255) / 256, 256>>>((const float4*)w1_w, (float4*)w1_r, nh4);
    round_tf32_kernel<<<(nh4 + 255) / 256, 256>>>((const float4*)w2_w, (float4*)w2_r, nh4);

    // 1. layernorms (tf32-rounded outputs)
    layernorm_kernel<<<TOK, 256>>>(x0, ln0_w, ln0_b, nq);
    layernorm_kernel<<<TOK, 256>>>(x1, ln1_w, ln1_b, nk);
    layernorm_kernel<<<TOK, 256>>>(x2, ln2_w, ln2_b, nv);
    layernorm_kernel<<<TOK, 256>>>(x3, ffn_w, ffn_b, fx);

    // 2. QKV projections
    dim3 gq(DMODEL / 128, TOK / 128);
    gemm_mma_kernel<ACT_NONE, false, false><<<gq, 256, GSMEM>>>(
        nq, wq_r, wq_b, nullptr, q, TOK, DMODEL, DMODEL);
    gemm_mma_kernel<ACT_NONE, false, false><<<gq, 256, GSMEM>>>(
        nk, wk_r, wk_b, nullptr, k, TOK, DMODEL, DMODEL);
    gemm_mma_kernel<ACT_NONE, false, false><<<gq, 256, GSMEM>>>(
        nv, wv_r, wv_b, nullptr, v, TOK, DMODEL, DMODEL);

    // 3. qk rmsnorm + rope
    qknorm_rope_kernel<<<TOK, 256>>>(q, qn_w, freqs);
    qknorm_rope_kernel<<<TOK, 256>>>(k, kn_w, freqs);

    // 4. causal attention (tf32-rounded output)
    attn_kernel<<<dim3(SEQ / 64, BATCH * NHEAD), 256>>>(q, k, v, y);

    // 5. o-projection + residual
    gemm_mma_kernel<ACT_NONE, true, false><<<gq, 256, GSMEM>>>(
        y, wo_r, wo_b, x3, hbuf, TOK, DMODEL, DMODEL);

    // 6. ffn1 + gelu (tf32-rounded output)
    dim3 g1(HID / 128, TOK / 128);
    gemm_mma_kernel<ACT_GELU, false, true><<<g1, 256, GSMEM>>>(
        fx, w1_r, w1_b, nullptr, ffn1, TOK, HID, DMODEL);

    // 7. ffn2 + residual -> final output
    gemm_mma_kernel<ACT_NONE, true, false><<<gq, 256, GSMEM>>>(
        ffn1, w2_r, w2_b, hbuf, out, TOK, DMODEL, HID);
}

// round 4
// speedup vs baseline: 4.6156x; 2.0781x over previous
#include <cuda_runtime.h>
#include <cuda_bf16.h>
#include <stdint.h>

#define BATCH 2
#define SEQ   2048
#define DMODEL 2048
#define NHEAD 16
#define HDIM  128
#define HID   5888
#define TOK   (BATCH*SEQ)            // 4096
#define CH    ((size_t)TOK*DMODEL)   // 8388608 floats
#define EPSV  1e-5f
#define SCALE_ATT 0.08838834764831845f   // 1/sqrt(128)

#define WQKVO_SZ ((size_t)DMODEL*DMODEL)
#define W12_SZ   ((size_t)HID*DMODEL)

// scratch: 9 act buffers + ffn1 + rounded weights
__device__ float g_scr[9*CH + (size_t)TOK*HID + 4*WQKVO_SZ + 2*W12_SZ];

// ---------------- helpers ---------------------------------------------------
__device__ __forceinline__ uint32_t smem_u32(const void* p) {
    uint32_t a;
    asm("{ .reg .u64 t; cvta.to.shared.u64 t, %1; cvt.u32.u64 %0, t; }"
        : "=r"(a) : "l"(p));
    return a;
}
__device__ __forceinline__ float f2tf32f(float x) {
    uint32_t r;
    asm("cvt.rna.tf32.f32 %0, %1;" : "=r"(r) : "f"(x));
    return __uint_as_float(r);
}
__device__ __forceinline__ void cpasync16(uint32_t dst, const void* src) {
    asm volatile("cp.async.cg.shared.global [%0], [%1], 16;" :: "r"(dst), "l"(src) : "memory");
}
#define CP_COMMIT() asm volatile("cp.async.commit_group;" ::: "memory")
#define CP_WAIT1()  asm volatile("cp.async.wait_group 1;" ::: "memory")

#define LDSM4(r, addr) \
    asm volatile("ldmatrix.sync.aligned.m8n8.x4.shared.b16 {%0,%1,%2,%3}, [%4];" \
        : "=r"((r)[0]), "=r"((r)[1]), "=r"((r)[2]), "=r"((r)[3]) : "r"(addr))

__device__ __forceinline__ uint32_t lds32(uint32_t a) {
    uint32_t v;
    asm volatile("ld.shared.b32 %0, [%1];" : "=r"(v) : "r"(a));
    return v;
}

__device__ __forceinline__ void mma_tf32(float (&c)[4], const uint32_t (&a)[4],
                                         uint32_t b0, uint32_t b1) {
    asm volatile(
        "mma.sync.aligned.m16n8k8.row.col.f32.tf32.tf32.f32 "
        "{%0,%1,%2,%3}, {%4,%5,%6,%7}, {%8,%9}, {%0,%1,%2,%3};\n"
        : "+f"(c[0]), "+f"(c[1]), "+f"(c[2]), "+f"(c[3])
        : "r"(a[0]), "r"(a[1]), "r"(a[2]), "r"(a[3]), "r"(b0), "r"(b1));
}

// ---------------- tf32 rounding pass (weights) ------------------------------
__global__ __launch_bounds__(256) void round_tf32_kernel(
    const float4* __restrict__ in, float4* __restrict__ out, int n4)
{
    const int i = blockIdx.x * 256 + threadIdx.x;
    if (i < n4) {
        float4 v = in[i];
        v.x = f2tf32f(v.x); v.y = f2tf32f(v.y);
        v.z = f2tf32f(v.z); v.w = f2tf32f(v.w);
        out[i] = v;
    }
}

// ---------------- layernorm (output rounded to tf32) ------------------------
__global__ __launch_bounds__(256) void layernorm_kernel(
    const float* __restrict__ x, const float* __restrict__ w,
    const float* __restrict__ b, float* __restrict__ out)
{
    const int row = blockIdx.x;
    const int t = threadIdx.x;
    const float4* xp = (const float4*)(x + (size_t)row * DMODEL);
    float4 v0 = xp[t], v1 = xp[t + 256];
    float s  = v0.x + v0.y + v0.z + v0.w + v1.x + v1.y + v1.z + v1.w;
    float ss = v0.x*v0.x + v0.y*v0.y + v0.z*v0.z + v0.w*v0.w
             + v1.x*v1.x + v1.y*v1.y + v1.z*v1.z + v1.w*v1.w;
    __shared__ float sred[16];
    const int lane = t & 31, warp = t >> 5;
#pragma unroll
    for (int o = 16; o; o >>= 1) {
        s  += __shfl_xor_sync(0xffffffffu, s,  o);
        ss += __shfl_xor_sync(0xffffffffu, ss, o);
    }
    if (lane == 0) { sred[warp] = s; sred[8 + warp] = ss; }
    __syncthreads();
    if (t < 32) {
        s  = (t < 8) ? sred[t]     : 0.f;
        ss = (t < 8) ? sred[8 + t] : 0.f;
#pragma unroll
        for (int o = 4; o; o >>= 1) {
            s  += __shfl_xor_sync(0xffffffffu, s,  o);
            ss += __shfl_xor_sync(0xffffffffu, ss, o);
        }
        if (t == 0) { sred[0] = s; sred[1] = ss; }
    }
    __syncthreads();
    const float mean = sred[0] * (1.f / DMODEL);
    const float var  = sred[1] * (1.f / DMODEL) - mean * mean;
    const float inv  = rsqrtf(var + EPSV);
    const float4* wp = (const float4*)w;
    const float4* bp = (const float4*)b;
    float4 w0 = wp[t], w1 = wp[t + 256], b0 = bp[t], b1 = bp[t + 256];
    float4 o0, o1;
    o0.x = f2tf32f((v0.x - mean) * inv * w0.x + b0.x);
    o0.y = f2tf32f((v0.y - mean) * inv * w0.y + b0.y);
    o0.z = f2tf32f((v0.z - mean) * inv * w0.z + b0.z);
    o0.w = f2tf32f((v0.w - mean) * inv * w0.w + b0.w);
    o1.x = f2tf32f((v1.x - mean) * inv * w1.x + b1.x);
    o1.y = f2tf32f((v1.y - mean) * inv * w1.y + b1.y);
    o1.z = f2tf32f((v1.z - mean) * inv * w1.z + b1.z);
    o1.w = f2tf32f((v1.w - mean) * inv * w1.w + b1.w);
    float4* op = (float4*)(out + (size_t)row * DMODEL);
    op[t] = o0;
    op[t + 256] = o1;
}

// ------- pipelined tf32 mma GEMM: C[M,N] = A[M,K] @ Bw[N,K]^T ---------------
// 128(M) x 256(N) CTA tile, BK=32, 3 stages, 8 warps of 64x64.
// gridDim.z selects fused sub-problems via aZ/wZ/cZ element strides.
#define ACT_NONE 0
#define ACT_GELU 1
#define GSTAGE 49152            // 48 KB per stage (A 16KB + B 32KB)
#define GSMEM  (3 * GSTAGE)     // 144 KB

template <int ACT, bool RES, bool ROUND>
__global__ __launch_bounds__(256, 1) void gemm_mma_kernel(
    const float* __restrict__ A, const float* __restrict__ Bw,
    const float* __restrict__ bias0, const float* __restrict__ bias1,
    const float* __restrict__ bias2, const float* __restrict__ Resid,
    float* __restrict__ C, int M, int N, int K,
    size_t aZ, size_t wZ, size_t cZ)
{
    extern __shared__ char smem[];
    const uint32_t s0 = smem_u32(smem);
    const int tid = threadIdx.x;
    const int warp = tid >> 5, lane = tid & 31;
    const int wm = (warp & 1) << 6;     // 0 / 64
    const int wn = (warp >> 1) << 6;    // 0,64,128,192
    const int mq = lane >> 3, l7 = lane & 7;
    const int z = blockIdx.z;
    const float* bias = (z == 0) ? bias0 : (z == 1) ? bias1 : bias2;
    const float* Ab = A  + (size_t)z * aZ + (size_t)(blockIdx.y * 128) * K;
    const float* Bb = Bw + (size_t)z * wZ + (size_t)(blockIdx.x * 256) * K;
    float* Cb = C + (size_t)z * cZ;
    const int nk = K >> 5;

#define G_LOAD(kt)                                                            \
    {                                                                         \
        const int st_ = (kt) % 3;                                             \
        const uint32_t sA_ = s0 + st_ * GSTAGE;                               \
        const uint32_t sB_ = sA_ + 16384;                                     \
        const size_t kof_ = (size_t)(kt) * 32;                                \
        _Pragma("unroll")                                                     \
        for (int p = 0; p < 4; ++p) {                                         \
            const int cid = tid + (p << 8);                                   \
            const int row = cid >> 3, c4 = cid & 7;                           \
            const uint32_t sw = row * 128 + ((c4 ^ (row & 7)) << 4);          \
            cpasync16(sA_ + sw, Ab + (size_t)row * K + kof_ + c4 * 4);        \
        }                                                                     \
        _Pragma("unroll")                                                     \
        for (int p = 0; p < 8; ++p) {                                         \
            const int cid = tid + (p << 8);                                   \
            const int row = cid >> 3, c4 = cid & 7;                           \
            const uint32_t sw = row * 128 + ((c4 ^ (row & 7)) << 4);          \
            cpasync16(sB_ + sw, Bb + (size_t)row * K + kof_ + c4 * 4);        \
        }                                                                     \
    }

    G_LOAD(0); CP_COMMIT();
    G_LOAD(1); CP_COMMIT();

    float acc[4][8][4];
#pragma unroll
    for (int i = 0; i < 4; i++)
#pragma unroll
        for (int j = 0; j < 8; j++)
#pragma unroll
            for (int r = 0; r < 4; r++) acc[i][j][r] = 0.f;

    for (int kt = 0; kt < nk; ++kt) {
        CP_WAIT1();
        __syncthreads();
        if (kt + 2 < nk) G_LOAD(kt + 2);
        CP_COMMIT();

        const uint32_t sA = s0 + (kt % 3) * GSTAGE, sB = sA + 16384;
#pragma unroll
        for (int kk = 0; kk < 4; ++kk) {
            uint32_t af[4][4], bf[4][4];
#pragma unroll
            for (int i = 0; i < 4; ++i) {
                const int row = wm + i * 16 + ((mq & 1) << 3) + l7;
                const int ch = (kk << 1) + (mq >> 1);
                LDSM4(af[i], sA + row * 128 + ((ch ^ (row & 7)) << 4));
            }
#pragma unroll
            for (int jp = 0; jp < 4; ++jp) {
                const int row = wn + jp * 16 + ((mq >> 1) << 3) + l7;
                const int ch = (kk << 1) + (mq & 1);
                LDSM4(bf[jp], sB + row * 128 + ((ch ^ (row & 7)) << 4));
            }
#pragma unroll
            for (int i = 0; i < 4; ++i)
#pragma unroll
                for (int j = 0; j < 8; ++j)
                    mma_tf32(acc[i][j], af[i],
                             bf[j >> 1][(j & 1) << 1], bf[j >> 1][((j & 1) << 1) + 1]);
        }
    }
#undef G_LOAD

    // epilogue
    const int g = lane >> 2, tg = lane & 3;
    const int rowbase = blockIdx.y * 128 + wm;
    const int colbase = blockIdx.x * 256 + wn;
#pragma unroll
    for (int i = 0; i < 4; ++i) {
#pragma unroll
        for (int j = 0; j < 8; ++j) {
            const int r0 = rowbase + i * 16 + g;
            const int c0 = colbase + j * 8 + tg * 2;
            const float bia0 = bias[c0], bia1 = bias[c0 + 1];
#pragma unroll
            for (int hr = 0; hr < 2; ++hr) {
                const int row = r0 + hr * 8;
                float v0 = acc[i][j][hr * 2 + 0] + bia0;
                float v1 = acc[i][j][hr * 2 + 1] + bia1;
                if (RES) {
                    v0 += Resid[(size_t)row * N + c0];
                    v1 += Resid[(size_t)row * N + c0 + 1];
                }
                if (ACT == ACT_GELU) {
                    v0 = 0.5f * v0 * (1.f + erff(v0 * 0.7071067811865475f));
                    v1 = 0.5f * v1 * (1.f + erff(v1 * 0.7071067811865475f));
                }
                if (ROUND) { v0 = f2tf32f(v0); v1 = f2tf32f(v1); }
                *(float2*)&Cb[(size_t)row * N + c0] = make_float2(v0, v1);
            }
        }
    }
}

// ---------------- per-head rmsnorm + rope (in-place, tf32-rounded out) ------
__global__ __launch_bounds__(256) void qknorm_rope_kernel(
    float* __restrict__ x, const float* __restrict__ w,
    const float* __restrict__ freqs)
{
    const int token = blockIdx.x;
    const int pos = token & (SEQ - 1);
    const int warp = threadIdx.x >> 5, lane = threadIdx.x & 31;
    __shared__ float rb[8][32];
    const float4 wv = ((const float4*)w)[lane];
#pragma unroll
    for (int hh = 0; hh < 2; hh++) {
        const int h = warp + hh * 8;
        float* p = x + (size_t)token * DMODEL + h * HDIM;
        float4 v = ((float4*)p)[lane];
        float ssq = v.x*v.x + v.y*v.y + v.z*v.z + v.w*v.w;
#pragma unroll
        for (int o = 16; o; o >>= 1) ssq += __shfl_xor_sync(0xffffffffu, ssq, o);
        const float inv = rsqrtf(ssq * (1.f / HDIM) + EPSV);
        float o0 = v.x * inv * wv.x, o1 = v.y * inv * wv.y;
        float o2 = v.z * inv * wv.z, o3 = v.w * inv * wv.w;
        const int d0 = lane * 4;
        if (d0 < 32) {
            rb[warp][d0] = o0; rb[warp][d0 + 1] = o1;
            rb[warp][d0 + 2] = o2; rb[warp][d0 + 3] = o3;
        }
        __syncwarp();
        if (d0 < 32) {
            float r[4];
#pragma unroll
            for (int i = 0; i < 4; i++) {
                const int d = d0 + i, ii = d >> 1;
                const float x1 = rb[warp][ii], x2 = rb[warp][ii + 16];
                const float c  = freqs[pos * 32 + ii * 2];
                const float sn = freqs[pos * 32 + ii * 2 + 1];
                r[i] = (d & 1) ? (x2 * c + x1 * sn) : (x1 * c - x2 * sn);
            }
            o0 = r[0]; o1 = r[1]; o2 = r[2]; o3 = r[3];
        }
        __syncwarp();
        ((float4*)p)[lane] = make_float4(f2tf32f(o0), f2tf32f(o1),
                                         f2tf32f(o2), f2tf32f(o3));
    }
}

// ---------------- causal flash attention (tf32 mma) -------------------------
// 64 q-rows per CTA, 4 warps (16 rows each), kv tiles of 32, 3-stage cp.async.
#define ASTAGE 32768            // K 16KB + V 16KB per stage
#define ASMEM  (3 * ASTAGE)     // 96 KB

__global__ __launch_bounds__(128, 2) void attn_mma_kernel(
    const float* __restrict__ Q, const float* __restrict__ Kx,
    const float* __restrict__ Vx, float* __restrict__ O)
{
    extern __shared__ char smem[];
    const uint32_t s0 = smem_u32(smem);
    const int tid = threadIdx.x;
    const int warp = tid >> 5, lane = tid & 31;
    const int g = lane >> 2, tg = lane & 3;
    const int mq = lane >> 3, l7 = lane & 7;
    const int qb = blockIdx.x, bh = blockIdx.y;
    const int b = bh >> 4, h = bh & 15;
    const size_t base = ((size_t)b * SEQ) * DMODEL + h * HDIM;
    const int q0 = qb * 64;
    const int wq = warp * 16;
    const int nkt = (q0 >> 5) + 2;

    // Q fragments (rows q0+wq+g / +8, 16 k-chunks over dim 128)
    uint32_t aq[16][4];
    {
        const float* q_r0 = Q + base + (size_t)(q0 + wq + g) * DMODEL;
        const float* q_r1 = q_r0 + (size_t)8 * DMODEL;
#pragma unroll
        for (int kk = 0; kk < 16; ++kk) {
            aq[kk][0] = __float_as_uint(q_r0[kk * 8 + tg]);
            aq[kk][1] = __float_as_uint(q_r1[kk * 8 + tg]);
            aq[kk][2] = __float_as_uint(q_r0[kk * 8 + tg + 4]);
            aq[kk][3] = __float_as_uint(q_r1[kk * 8 + tg + 4]);
        }
    }

#define A_LOAD(kt)                                                            \
    {                                                                         \
        const int st_ = (kt) % 3;                                             \
        const uint32_t Kst_ = s0 + st_ * ASTAGE;                              \
        const uint32_t Vst_ = Kst_ + 16384;                                   \
        const int kv0_ = (kt) << 5;                                           \
        _Pragma("unroll")                                                     \
        for (int p = 0; p < 8; ++p) {                                         \
            const int cid = tid + (p << 7);                                   \
            const int row = cid >> 5, c = cid & 31;                           \
            const uint32_t sw = row * 512 + ((c ^ (row & 7)) << 4);           \
            const size_t go = base + (size_t)(kv0_ + row) * DMODEL + c * 4;   \
            cpasync16(Kst_ + sw, Kx + go);                                    \
            cpasync16(Vst_ + sw, Vx + go);                                    \
        }                                                                     \
    }

    A_LOAD(0); CP_COMMIT();
    A_LOAD(1); CP_COMMIT();

    float m0 = -1e30f, m1 = -1e30f, l0 = 0.f, l1 = 0.f;
    float o[16][4];
#pragma unroll
    for (int nb = 0; nb < 16; ++nb)
#pragma unroll
        for (int r = 0; r < 4; ++r) o[nb][r] = 0.f;

    const int r0 = q0 + wq + g, r1 = r0 + 8;

    for (int kt = 0; kt < nkt; ++kt) {
        CP_WAIT1();
        __syncthreads();
        if (kt + 2 < nkt) A_LOAD(kt + 2);
        CP_COMMIT();

        const int kv0 = kt << 5;
        if (kv0 <= q0 + wq + 15) {
            const uint32_t Kst = s0 + (kt % 3) * ASTAGE;
            const uint32_t Vst = Kst + 16384;

            // ---- S = Q @ K^T ----
            float sc[4][4];
#pragma unroll
            for (int jb = 0; jb < 4; ++jb)
#pragma unroll
                for (int r = 0; r < 4; ++r) sc[jb][r] = 0.f;
#pragma unroll
            for (int kk = 0; kk < 16; ++kk) {
                uint32_t bf[2][4];
#pragma unroll
                for (int jp = 0; jp < 2; ++jp) {
                    const int row = jp * 16 + ((mq >> 1) << 3) + l7;
                    const int ch = (kk << 1) + (mq & 1);
                    LDSM4(bf[jp], Kst + row * 512 + ((ch ^ (row & 7)) << 4));
                }
#pragma unroll
                for (int jb = 0; jb < 4; ++jb)
                    mma_tf32(sc[jb], aq[kk],
                             bf[jb >> 1][(jb & 1) << 1], bf[jb >> 1][((jb & 1) << 1) + 1]);
            }

            // ---- scale + causal mask ----
            const bool diag = (kv0 + 31 > r0) || (kv0 + 31 > r1);
#pragma unroll
            for (int jb = 0; jb < 4; ++jb) {
                const int c0 = kv0 + jb * 8 + tg * 2;
                sc[jb][0] *= SCALE_ATT; sc[jb][1] *= SCALE_ATT;
                sc[jb][2] *= SCALE_ATT; sc[jb][3] *= SCALE_ATT;
                if (diag) {
                    if (c0     > r0) sc[jb][0] = -1e30f;
                    if (c0 + 1 > r0) sc[jb][1] = -1e30f;
                    if (c0     > r1) sc[jb][2] = -1e30f;
                    if (c0 + 1 > r1) sc[jb][3] = -1e30f;
                }
            }

            // ---- online softmax ----
            float rm0 = sc[0][0], rm1 = sc[0][2];
#pragma unroll
            for (int jb = 0; jb < 4; ++jb) {
                rm0 = fmaxf(rm0, fmaxf(sc[jb][0], sc[jb][1]));
                rm1 = fmaxf(rm1, fmaxf(sc[jb][2], sc[jb][3]));
            }
            rm0 = fmaxf(rm0, __shfl_xor_sync(0xffffffffu, rm0, 1));
            rm0 = fmaxf(rm0, __shfl_xor_sync(0xffffffffu, rm0, 2));
            rm1 = fmaxf(rm1, __shfl_xor_sync(0xffffffffu, rm1, 1));
            rm1 = fmaxf(rm1, __shfl_xor_sync(0xffffffffu, rm1, 2));
            const float mx0 = fmaxf(m0, rm0), mx1 = fmaxf(m1, rm1);
            const float corr0 = __expf(m0 - mx0), corr1 = __expf(m1 - mx1);
            float rs0 = 0.f, rs1 = 0.f;
#pragma unroll
            for (int jb = 0; jb < 4; ++jb) {
                sc[jb][0] = f2tf32f(__expf(sc[jb][0] - mx0));
                sc[jb][1] = f2tf32f(__expf(sc[jb][1] - mx0));
                sc[jb][2] = f2tf32f(__expf(sc[jb][2] - mx1));
                sc[jb][3] = f2tf32f(__expf(sc[jb][3] - mx1));
                rs0 += sc[jb][0] + sc[jb][1];
                rs1 += sc[jb][2] + sc[jb][3];
            }
            rs0 += __shfl_xor_sync(0xffffffffu, rs0, 1);
            rs0 += __shfl_xor_sync(0xffffffffu, rs0, 2);
            rs1 += __shfl_xor_sync(0xffffffffu, rs1, 1);
            rs1 += __shfl_xor_sync(0xffffffffu, rs1, 2);
            l0 = l0 * corr0 + rs0;  m0 = mx0;
            l1 = l1 * corr1 + rs1;  m1 = mx1;
#pragma unroll
            for (int nb = 0; nb < 16; ++nb) {
                o[nb][0] *= corr0; o[nb][1] *= corr0;
                o[nb][2] *= corr1; o[nb][3] *= corr1;
            }

            // ---- O += P @ V ----
            const int srcA = (g << 2) + (tg >> 1);
            const int srcB = srcA + 2;
            const bool hi = (tg & 1);
#pragma unroll
            for (int kc = 0; kc < 4; ++kc) {
                uint32_t pa[4];
                float x0, x1;
                x0 = __shfl_sync(0xffffffffu, sc[kc][0], srcA);
                x1 = __shfl_sync(0xffffffffu, sc[kc][1], srcA);
                pa[0] = __float_as_uint(hi ? x1 : x0);
                x0 = __shfl_sync(0xffffffffu, sc[kc][2], srcA);
                x1 = __shfl_sync(0xffffffffu, sc[kc][3], srcA);
                pa[1] = __float_as_uint(hi ? x1 : x0);
                x0 = __shfl_sync(0xffffffffu, sc[kc][0], srcB);
                x1 = __shfl_sync(0xffffffffu, sc[kc][1], srcB);
                pa[2] = __float_as_uint(hi ? x1 : x0);
                x0 = __shfl_sync(0xffffffffu, sc[kc][2], srcB);
                x1 = __shfl_sync(0xffffffffu, sc[kc][3], srcB);
                pa[3] = __float_as_uint(hi ? x1 : x0);

                const int vr0 = kc * 8 + tg, vr1 = vr0 + 4;
                const uint32_t vb0 = Vst + vr0 * 512 + (g & 3) * 4;
                const uint32_t vb1 = Vst + vr1 * 512 + (g & 3) * 4;
                const int m0c = vr0 & 7, m1c = vr1 & 7;
                const int gch = g >> 2;
#pragma unroll
                for (int nb = 0; nb < 16; ++nb) {
                    const int ch = nb * 2 + gch;
                    const uint32_t b0 = lds32(vb0 + ((ch ^ m0c) << 4));
                    const uint32_t b1 = lds32(vb1 + ((ch ^ m1c) << 4));
                    mma_tf32(o[nb], pa, b0, b1);
                }
            }
        }
    }
#undef A_LOAD

    // ---- write O ----
    const float inv0 = 1.f / l0, inv1 = 1.f / l1;
    float* o_r0 = O + base + (size_t)r0 * DMODEL;
    float* o_r1 = O + base + (size_t)r1 * DMODEL;
#pragma unroll
    for (int nb = 0; nb < 16; ++nb) {
        const int c = nb * 8 + tg * 2;
        *(float2*)&o_r0[c] = make_float2(f2tf32f(o[nb][0] * inv0),
                                         f2tf32f(o[nb][1] * inv0));
        *(float2*)&o_r1[c] = make_float2(f2tf32f(o[nb][2] * inv1),
                                         f2tf32f(o[nb][3] * inv1));
    }
}

// ---------------- launcher --------------------------------------------------
extern "C" void kernel_launch(void* const* d_in, const int* in_sizes, int n_in,
                              void* d_out, int out_size)
{
    const float* x0      = (const float*)d_in[0];
    const float* x1      = (const float*)d_in[1];
    const float* x2      = (const float*)d_in[2];
    const float* x3      = (const float*)d_in[3];
    const float* freqs   = (const float*)d_in[5];
    const float* wq_w    = (const float*)d_in[7];
    const float* wq_b    = (const float*)d_in[8];
    const float* wk_w    = (const float*)d_in[9];
    const float* wk_b    = (const float*)d_in[10];
    const float* wv_w    = (const float*)d_in[11];
    const float* wv_b    = (const float*)d_in[12];
    const float* wo_w    = (const float*)d_in[13];
    const float* wo_b    = (const float*)d_in[14];
    const float* qn_w    = (const float*)d_in[15];
    const float* kn_w    = (const float*)d_in[16];
    const float* ln0_w   = (const float*)d_in[17];
    const float* ln0_b   = (const float*)d_in[18];
    const float* ln1_w   = (const float*)d_in[19];
    const float* ln1_b   = (const float*)d_in[20];
    const float* ln2_w   = (const float*)d_in[21];
    const float* ln2_b   = (const float*)d_in[22];
    const float* ffn_w   = (const float*)d_in[23];
    const float* ffn_b   = (const float*)d_in[24];
    const float* w1_w    = (const float*)d_in[25];
    const float* w1_b    = (const float*)d_in[26];
    const float* w2_w    = (const float*)d_in[27];
    const float* w2_b    = (const float*)d_in[28];
    float* out = (float*)d_out;

    float* scr = nullptr;
    cudaGetSymbolAddress((void**)&scr, g_scr);
    float* nq   = scr + 0 * CH;
    float* nv   = scr + 2 * CH;
    float* fx   = scr + 3 * CH;
    float* q    = scr + 4 * CH;
    float* k    = scr + 5 * CH;
    float* v    = scr + 6 * CH;
    float* y    = scr + 7 * CH;
    float* hbuf = scr + 8 * CH;
    float* ffn1 = scr + 9 * CH;
    float* wq_r = ffn1 + (size_t)TOK * HID;
    float* wk_r = wq_r + WQKVO_SZ;
    float* wv_r = wk_r + WQKVO_SZ;
    float* wo_r = wv_r + WQKVO_SZ;
    float* w1_r = wo_r + WQKVO_SZ;
    float* w2_r = w1_r + W12_SZ;
    (void)nv;

    cudaFuncSetAttribute(gemm_mma_kernel<ACT_NONE, false, true>,
                         cudaFuncAttributeMaxDynamicSharedMemorySize, GSMEM);
    cudaFuncSetAttribute(gemm_mma_kernel<ACT_NONE, true, false>,
                         cudaFuncAttributeMaxDynamicSharedMemorySize, GSMEM);
    cudaFuncSetAttribute(gemm_mma_kernel<ACT_GELU, false, true>,
                         cudaFuncAttributeMaxDynamicSharedMemorySize, GSMEM);
    cudaFuncSetAttribute(attn_mma_kernel,
                         cudaFuncAttributeMaxDynamicSharedMemorySize, ASMEM);

    // 0. round weights to tf32
    const int nw4 = (int)(WQKVO_SZ / 4), nh4 = (int)(W12_SZ / 4);
    round_tf32_kernel<<<(nw4 + 255) / 256, 256>>>((const float4*)wq_w, (float4*)wq_r, nw4);
    round_tf32_kernel<<<(nw4 + 255) / 256, 256>>>((const float4*)wk_w, (float4*)wk_r, nw4);
    round_tf32_kernel<<<(nw4 + 255) / 256, 256>>>((const float4*)wv_w, (float4*)wv_r, nw4);
    round_tf32_kernel<<<(nw4 + 255) / 256, 256>>>((const float4*)wo_w, (float4*)wo_r, nw4);
    round_tf32_kernel<<<(nh4 + 255) / 256, 256>>>((const float4*)w1_w, (float4*)w1_r, nh4);
    round_tf32_kernel<<<(nh4 + 255) / 256, 256>>>((const float4*)w2_w, (float4*)w2_r, nh4);

    // 1. layernorms (nq, nk, nv contiguous from nq)
    layernorm_kernel<<<TOK, 256>>>(x0, ln0_w, ln0_b, nq);
    layernorm_kernel<<<TOK, 256>>>(x1, ln1_w, ln1_b, nq + CH);
    layernorm_kernel<<<TOK, 256>>>(x2, ln2_w, ln2_b, nq + 2 * CH);
    layernorm_kernel<<<TOK, 256>>>(x3, ffn_w, ffn_b, fx);

    // 2. fused QKV projection (z selects q/k/v)
    dim3 gqkv(DMODEL / 256, TOK / 128, 3);
    gemm_mma_kernel<ACT_NONE, false, true><<<gqkv, 256, GSMEM>>>(
        nq, wq_r, wq_b, wk_b, wv_b, nullptr, q,
        TOK, DMODEL, DMODEL, CH, WQKVO_SZ, CH);

    // 3. qk rmsnorm + rope (tf32-rounded)
    qknorm_rope_kernel<<<TOK, 256>>>(q, qn_w, freqs);
    qknorm_rope_kernel<<<TOK, 256>>>(k, kn_w, freqs);

    // 4. causal attention (tf32 mma, tf32-rounded output)
    attn_mma_kernel<<<dim3(SEQ / 64, BATCH * NHEAD), 128, ASMEM>>>(q, k, v, y);

    // 5. o-projection + residual
    dim3 go(DMODEL / 256, TOK / 128, 1);
    gemm_mma_kernel<ACT_NONE, true, false><<<go, 256, GSMEM>>>(
        y, wo_r, wo_b, nullptr, nullptr, x3, hbuf,
        TOK, DMODEL, DMODEL, 0, 0, 0);

    // 6. ffn1 + gelu (tf32-rounded output)
    dim3 g1(HID / 256, TOK / 128, 1);
    gemm_mma_kernel<ACT_GELU, false, true><<<g1, 256, GSMEM>>>(
        fx, w1_r, w1_b, nullptr, nullptr, nullptr, ffn1,
        TOK, HID, DMODEL, 0, 0, 0);

    // 7. ffn2 + residual -> final output
    gemm_mma_kernel<ACT_NONE, true, false><<<go, 256, GSMEM>>>(
        ffn1, w2_r, w2_b, nullptr, nullptr, hbuf, out,
        TOK, DMODEL, HID, 0, 0, 0);
}

// round 5
// speedup vs baseline: 7.5769x; 1.6416x over previous
#include <cuda_runtime.h>
#include <cuda_fp16.h>
#include <stdint.h>

#define BATCH 2
#define SEQ   2048
#define DMODEL 2048
#define NHEAD 16
#define HDIM  128
#define HID   5888
#define TOK   (BATCH*SEQ)            // 4096
#define CH    ((size_t)TOK*DMODEL)   // 8388608
#define EPSV  1e-5f
#define SCALE_ATT 0.08838834764831845f

#define WQKVO_SZ ((size_t)DMODEL*DMODEL)
#define W12_SZ   ((size_t)HID*DMODEL)
#define HTOT (8*CH + (size_t)TOK*HID + 4*WQKVO_SZ + 2*W12_SZ)

__device__ __half g_h[HTOT];     // half scratch: activations + converted weights
__device__ float g_fbuf[CH];     // fp32 residual buffer (hbuf)

// ---------------- helpers ---------------------------------------------------
__device__ __forceinline__ uint32_t smem_u32(const void* p) {
    uint32_t a;
    asm("{ .reg .u64 t; cvta.to.shared.u64 t, %1; cvt.u32.u64 %0, t; }"
        : "=r"(a) : "l"(p));
    return a;
}
__device__ __forceinline__ uint32_t packh2(float a, float b) {
    __half2 h = __floats2half2_rn(a, b);
    return *(uint32_t*)&h;
}
__device__ __forceinline__ void cpasync16(uint32_t dst, const void* src) {
    asm volatile("cp.async.cg.shared.global [%0], [%1], 16;" :: "r"(dst), "l"(src) : "memory");
}
#define CP_COMMIT() asm volatile("cp.async.commit_group;" ::: "memory")
#define CP_WAIT1()  asm volatile("cp.async.wait_group 1;" ::: "memory")

#define LDSM4(r, addr) \
    asm volatile("ldmatrix.sync.aligned.m8n8.x4.shared.b16 {%0,%1,%2,%3}, [%4];" \
        : "=r"((r)[0]), "=r"((r)[1]), "=r"((r)[2]), "=r"((r)[3]) : "r"(addr))
#define LDSM4T(r, addr) \
    asm volatile("ldmatrix.sync.aligned.m8n8.x4.trans.shared.b16 {%0,%1,%2,%3}, [%4];" \
        : "=r"((r)[0]), "=r"((r)[1]), "=r"((r)[2]), "=r"((r)[3]) : "r"(addr))

__device__ __forceinline__ void mma_h(float (&c)[4], const uint32_t (&a)[4],
                                      uint32_t b0, uint32_t b1) {
    asm volatile(
        "mma.sync.aligned.m16n8k16.row.col.f32.f16.f16.f32 "
        "{%0,%1,%2,%3}, {%4,%5,%6,%7}, {%8,%9}, {%0,%1,%2,%3};\n"
        : "+f"(c[0]), "+f"(c[1]), "+f"(c[2]), "+f"(c[3])
        : "r"(a[0]), "r"(a[1]), "r"(a[2]), "r"(a[3]), "r"(b0), "r"(b1));
}

// ---------------- fp32 -> fp16 weight conversion ----------------------------
__global__ __launch_bounds__(256) void round_h_kernel(
    const float4* __restrict__ in, uint2* __restrict__ out, int n4)
{
    const int i = blockIdx.x * 256 + threadIdx.x;
    if (i < n4) {
        float4 v = in[i];
        uint2 u;
        u.x = packh2(v.x, v.y);
        u.y = packh2(v.z, v.w);
        out[i] = u;
    }
}

// ---------------- layernorm (fp32 in, fp16 out) -----------------------------
__global__ __launch_bounds__(256) void layernorm_kernel(
    const float* __restrict__ x, const float* __restrict__ w,
    const float* __restrict__ b, __half* __restrict__ out)
{
    const int row = blockIdx.x;
    const int t = threadIdx.x;
    const float4* xp = (const float4*)(x + (size_t)row * DMODEL);
    float4 v0 = xp[t], v1 = xp[t + 256];
    float s  = v0.x + v0.y + v0.z + v0.w + v1.x + v1.y + v1.z + v1.w;
    float ss = v0.x*v0.x + v0.y*v0.y + v0.z*v0.z + v0.w*v0.w
             + v1.x*v1.x + v1.y*v1.y + v1.z*v1.z + v1.w*v1.w;
    __shared__ float sred[16];
    const int lane = t & 31, warp = t >> 5;
#pragma unroll
    for (int o = 16; o; o >>= 1) {
        s  += __shfl_xor_sync(0xffffffffu, s,  o);
        ss += __shfl_xor_sync(0xffffffffu, ss, o);
    }
    if (lane == 0) { sred[warp] = s; sred[8 + warp] = ss; }
    __syncthreads();
    if (t < 32) {
        s  = (t < 8) ? sred[t]     : 0.f;
        ss = (t < 8) ? sred[8 + t] : 0.f;
#pragma unroll
        for (int o = 4; o; o >>= 1) {
            s  += __shfl_xor_sync(0xffffffffu, s,  o);
            ss += __shfl_xor_sync(0xffffffffu, ss, o);
        }
        if (t == 0) { sred[0] = s; sred[1] = ss; }
    }
    __syncthreads();
    const float mean = sred[0] * (1.f / DMODEL);
    const float var  = sred[1] * (1.f / DMODEL) - mean * mean;
    const float inv  = rsqrtf(var + EPSV);
    const float4* wp = (const float4*)w;
    const float4* bp = (const float4*)b;
    float4 w0 = wp[t], w1 = wp[t + 256], b0 = bp[t], b1 = bp[t + 256];
    uint2 o0, o1;
    o0.x = packh2((v0.x - mean) * inv * w0.x + b0.x, (v0.y - mean) * inv * w0.y + b0.y);
    o0.y = packh2((v0.z - mean) * inv * w0.z + b0.z, (v0.w - mean) * inv * w0.w + b0.w);
    o1.x = packh2((v1.x - mean) * inv * w1.x + b1.x, (v1.y - mean) * inv * w1.y + b1.y);
    o1.y = packh2((v1.z - mean) * inv * w1.z + b1.z, (v1.w - mean) * inv * w1.w + b1.w);
    uint2* op = (uint2*)(out + (size_t)row * DMODEL);
    op[t] = o0;
    op[t + 256] = o1;
}

// ------- pipelined fp16 mma GEMM: C[M,N] = A[M,K] @ Bw[N,K]^T ---------------
// 128(M) x 256(N) CTA tile, BK=64 halves (128B rows), 3 stages, 8 warps 64x64.
#define ACT_NONE 0
#define ACT_GELU 1
#define GSTAGE 49152            // A 16KB + B 32KB
#define GSMEM  (3 * GSTAGE)     // 144 KB

template <int ACT, bool RES, bool OUTH>
__global__ __launch_bounds__(256, 1) void gemm_h_kernel(
    const __half* __restrict__ A, const __half* __restrict__ Bw,
    const float* __restrict__ bias0, const float* __restrict__ bias1,
    const float* __restrict__ bias2, const float* __restrict__ Resid,
    void* __restrict__ Cv, int M, int N, int K,
    size_t aZ, size_t wZ, size_t cZ)
{
    extern __shared__ char smem[];
    const uint32_t s0 = smem_u32(smem);
    const int tid = threadIdx.x;
    const int warp = tid >> 5, lane = tid & 31;
    const int wm = (warp & 1) << 6;
    const int wn = (warp >> 1) << 6;
    const int l15 = lane & 15, lh = lane >> 4;
    const int z = blockIdx.z;
    const float* bias = (z == 0) ? bias0 : (z == 1) ? bias1 : bias2;
    const __half* Ab = A  + (size_t)z * aZ + (size_t)(blockIdx.y * 128) * K;
    const __half* Bb = Bw + (size_t)z * wZ + (size_t)(blockIdx.x * 256) * K;
    const int nk = K >> 6;

#define G_LOAD(kt)                                                            \
    {                                                                         \
        const int st_ = (kt) % 3;                                             \
        const uint32_t sA_ = s0 + st_ * GSTAGE;                               \
        const uint32_t sB_ = sA_ + 16384;                                     \
        const size_t kof_ = (size_t)(kt) * 64;                                \
        _Pragma("unroll")                                                     \
        for (int p = 0; p < 4; ++p) {                                         \
            const int cid = tid + (p << 8);                                   \
            const int row = cid >> 3, c4 = cid & 7;                           \
            const uint32_t sw = row * 128 + ((c4 ^ (row & 7)) << 4);          \
            cpasync16(sA_ + sw, Ab + (size_t)row * K + kof_ + c4 * 8);        \
        }                                                                     \
        _Pragma("unroll")                                                     \
        for (int p = 0; p < 8; ++p) {                                         \
            const int cid = tid + (p << 8);                                   \
            const int row = cid >> 3, c4 = cid & 7;                           \
            const uint32_t sw = row * 128 + ((c4 ^ (row & 7)) << 4);          \
            cpasync16(sB_ + sw, Bb + (size_t)row * K + kof_ + c4 * 8);        \
        }                                                                     \
    }

    G_LOAD(0); CP_COMMIT();
    G_LOAD(1); CP_COMMIT();

    float acc[4][8][4];
#pragma unroll
    for (int i = 0; i < 4; i++)
#pragma unroll
        for (int j = 0; j < 8; j++)
#pragma unroll
            for (int r = 0; r < 4; r++) acc[i][j][r] = 0.f;

    for (int kt = 0; kt < nk; ++kt) {
        CP_WAIT1();
        __syncthreads();
        if (kt + 2 < nk) G_LOAD(kt + 2);
        CP_COMMIT();

        const uint32_t sA = s0 + (kt % 3) * GSTAGE, sB = sA + 16384;
#pragma unroll
        for (int kk = 0; kk < 4; ++kk) {
            uint32_t af[4][4], bf[4][4];
            const int ch = (kk << 1) + lh;
#pragma unroll
            for (int i = 0; i < 4; ++i) {
                const int row = wm + i * 16 + l15;
                LDSM4(af[i], sA + row * 128 + ((ch ^ (row & 7)) << 4));
            }
#pragma unroll
            for (int jp = 0; jp < 4; ++jp) {
                const int row = wn + jp * 16 + l15;
                LDSM4(bf[jp], sB + row * 128 + ((ch ^ (row & 7)) << 4));
            }
#pragma unroll
            for (int i = 0; i < 4; ++i)
#pragma unroll
                for (int jp = 0; jp < 4; ++jp) {
                    mma_h(acc[i][2*jp],   af[i], bf[jp][0], bf[jp][2]);
                    mma_h(acc[i][2*jp+1], af[i], bf[jp][1], bf[jp][3]);
                }
        }
    }
#undef G_LOAD

    // epilogue
    const int g = lane >> 2, tg = lane & 3;
    const int rowbase = blockIdx.y * 128 + wm;
    const int colbase = blockIdx.x * 256 + wn;
#pragma unroll
    for (int i = 0; i < 4; ++i) {
#pragma unroll
        for (int j = 0; j < 8; ++j) {
            const int r0 = rowbase + i * 16 + g;
            const int c0 = colbase + j * 8 + tg * 2;
            const float bia0 = bias[c0], bia1 = bias[c0 + 1];
#pragma unroll
            for (int hr = 0; hr < 2; ++hr) {
                const int row = r0 + hr * 8;
                float v0 = acc[i][j][hr * 2 + 0] + bia0;
                float v1 = acc[i][j][hr * 2 + 1] + bia1;
                if (RES) {
                    v0 += Resid[(size_t)row * N + c0];
                    v1 += Resid[(size_t)row * N + c0 + 1];
                }
                if (ACT == ACT_GELU) {
                    v0 = 0.5f * v0 * (1.f + erff(v0 * 0.7071067811865475f));
                    v1 = 0.5f * v1 * (1.f + erff(v1 * 0.7071067811865475f));
                }
                if (OUTH) {
                    __half* Cb = (__half*)Cv + (size_t)z * cZ;
                    *(uint32_t*)&Cb[(size_t)row * N + c0] = packh2(v0, v1);
                } else {
                    float* Cb = (float*)Cv + (size_t)z * cZ;
                    *(float2*)&Cb[(size_t)row * N + c0] = make_float2(v0, v1);
                }
            }
        }
    }
}

// ---------------- per-head rmsnorm + rope (fp16 in-place) -------------------
__global__ __launch_bounds__(256) void qknorm_rope_kernel(
    __half* __restrict__ q, __half* __restrict__ k,
    const float* __restrict__ qn, const float* __restrict__ kn,
    const float* __restrict__ freqs)
{
    const int token = blockIdx.x;
    __half* x = blockIdx.y ? k : q;
    const float* w = blockIdx.y ? kn : qn;
    const int pos = token & (SEQ - 1);
    const int warp = threadIdx.x >> 5, lane = threadIdx.x & 31;
    __shared__ float rb[8][32];
    const float4 wv = ((const float4*)w)[lane];
#pragma unroll
    for (int hh = 0; hh < 2; hh++) {
        const int h = warp + hh * 8;
        __half* p = x + (size_t)token * DMODEL + h * HDIM;
        uint2 raw = ((uint2*)p)[lane];
        const __half2 h0 = *(__half2*)&raw.x, h1 = *(__half2*)&raw.y;
        float v0 = __low2float(h0), v1 = __high2float(h0);
        float v2 = __low2float(h1), v3 = __high2float(h1);
        float ssq = v0*v0 + v1*v1 + v2*v2 + v3*v3;
#pragma unroll
        for (int o = 16; o; o >>= 1) ssq += __shfl_xor_sync(0xffffffffu, ssq, o);
        const float inv = rsqrtf(ssq * (1.f / HDIM) + EPSV);
        float o0 = v0 * inv * wv.x, o1 = v1 * inv * wv.y;
        float o2 = v2 * inv * wv.z, o3 = v3 * inv * wv.w;
        const int d0 = lane * 4;
        if (d0 < 32) {
            rb[warp][d0] = o0; rb[warp][d0 + 1] = o1;
            rb[warp][d0 + 2] = o2; rb[warp][d0 + 3] = o3;
        }
        __syncwarp();
        if (d0 < 32) {
            float r[4];
#pragma unroll
            for (int i = 0; i < 4; i++) {
                const int d = d0 + i, ii = d >> 1;
                const float x1 = rb[warp][ii], x2 = rb[warp][ii + 16];
                const float c  = freqs[pos * 32 + ii * 2];
                const float sn = freqs[pos * 32 + ii * 2 + 1];
                r[i] = (d & 1) ? (x2 * c + x1 * sn) : (x1 * c - x2 * sn);
            }
            o0 = r[0]; o1 = r[1]; o2 = r[2]; o3 = r[3];
        }
        __syncwarp();
        raw.x = packh2(o0, o1);
        raw.y = packh2(o2, o3);
        ((uint2*)p)[lane] = raw;
    }
}

// ---------------- causal flash attention (fp16 mma) -------------------------
// 64 q-rows/CTA, 4 warps (16 rows each), kv tiles of 32, 3-stage cp.async.
#define ASTAGE 16384            // K 8KB + V 8KB
#define ASMEM  (3 * ASTAGE)     // 48 KB

__global__ __launch_bounds__(128, 3) void attn_h_kernel(
    const __half* __restrict__ Q, const __half* __restrict__ Kx,
    const __half* __restrict__ Vx, __half* __restrict__ O)
{
    extern __shared__ char smem[];
    const uint32_t s0 = smem_u32(smem);
    const int tid = threadIdx.x;
    const int warp = tid >> 5, lane = tid & 31;
    const int g = lane >> 2, tg = lane & 3;
    const int l15 = lane & 15, lh = lane >> 4;
    const int qb = blockIdx.x, bh = blockIdx.y;
    const int b = bh >> 4, h = bh & 15;
    const size_t base = ((size_t)b * SEQ) * DMODEL + h * HDIM;
    const int q0 = qb * 64;
    const int wq = warp * 16;
    const int nkt = (q0 >> 5) + 2;
    const int r0 = q0 + wq + g, r1 = r0 + 8;

    // Q fragments: 8 k16-chunks over d=128
    uint32_t aq[8][4];
    {
        const __half* q_r0 = Q + base + (size_t)r0 * DMODEL;
        const __half* q_r1 = q_r0 + (size_t)8 * DMODEL;
#pragma unroll
        for (int kk = 0; kk < 8; ++kk) {
            aq[kk][0] = *(const uint32_t*)(q_r0 + kk * 16 + tg * 2);
            aq[kk][1] = *(const uint32_t*)(q_r1 + kk * 16 + tg * 2);
            aq[kk][2] = *(const uint32_t*)(q_r0 + kk * 16 + 8 + tg * 2);
            aq[kk][3] = *(const uint32_t*)(q_r1 + kk * 16 + 8 + tg * 2);
        }
    }

#define A_LOAD(kt)                                                            \
    {                                                                         \
        const int st_ = (kt) % 3;                                             \
        const uint32_t Kst_ = s0 + st_ * ASTAGE;                              \
        const uint32_t Vst_ = Kst_ + 8192;                                    \
        const int kv0_ = (kt) << 5;                                           \
        _Pragma("unroll")                                                     \
        for (int p = 0; p < 4; ++p) {                                         \
            const int cid = tid + (p << 7);                                   \
            const int row = cid >> 4, c = cid & 15;                           \
            const uint32_t sw = row * 256 + ((c ^ (row & 7)) << 4);           \
            const size_t go = base + (size_t)(kv0_ + row) * DMODEL + c * 8;   \
            cpasync16(Kst_ + sw, Kx + go);                                    \
            cpasync16(Vst_ + sw, Vx + go);                                    \
        }                                                                     \
    }

    A_LOAD(0); CP_COMMIT();
    A_LOAD(1); CP_COMMIT();

    float m0 = -1e30f, m1 = -1e30f, l0 = 0.f, l1 = 0.f;
    float o[16][4];
#pragma unroll
    for (int nb = 0; nb < 16; ++nb)
#pragma unroll
        for (int r = 0; r < 4; ++r) o[nb][r] = 0.f;

    for (int kt = 0; kt < nkt; ++kt) {
        CP_WAIT1();
        __syncthreads();
        if (kt + 2 < nkt) A_LOAD(kt + 2);
        CP_COMMIT();

        const int kv0 = kt << 5;
        if (kv0 <= q0 + wq + 15) {
            const uint32_t Kst = s0 + (kt % 3) * ASTAGE;
            const uint32_t Vst = Kst + 8192;

            // ---- S = Q @ K^T ----
            float sc[4][4];
#pragma unroll
            for (int jb = 0; jb < 4; ++jb)
#pragma unroll
                for (int r = 0; r < 4; ++r) sc[jb][r] = 0.f;
#pragma unroll
            for (int kk = 0; kk < 8; ++kk) {
                const int ch = (kk << 1) + lh;
#pragma unroll
                for (int jp = 0; jp < 2; ++jp) {
                    uint32_t bf[4];
                    const int row = jp * 16 + l15;
                    LDSM4(bf, Kst + row * 256 + ((ch ^ (row & 7)) << 4));
                    mma_h(sc[2*jp],   aq[kk], bf[0], bf[2]);
                    mma_h(sc[2*jp+1], aq[kk], bf[1], bf[3]);
                }
            }

            // ---- scale + causal mask ----
            const bool diag = (kv0 + 31 > r0) || (kv0 + 31 > r1);
#pragma unroll
            for (int jb = 0; jb < 4; ++jb) {
                const int c0 = kv0 + jb * 8 + tg * 2;
                sc[jb][0] *= SCALE_ATT; sc[jb][1] *= SCALE_ATT;
                sc[jb][2] *= SCALE_ATT; sc[jb][3] *= SCALE_ATT;
                if (diag) {
                    if (c0     > r0) sc[jb][0] = -1e30f;
                    if (c0 + 1 > r0) sc[jb][1] = -1e30f;
                    if (c0     > r1) sc[jb][2] = -1e30f;
                    if (c0 + 1 > r1) sc[jb][3] = -1e30f;
                }
            }

            // ---- online softmax ----
            float rm0 = sc[0][0], rm1 = sc[0][2];
#pragma unroll
            for (int jb = 0; jb < 4; ++jb) {
                rm0 = fmaxf(rm0, fmaxf(sc[jb][0], sc[jb][1]));
                rm1 = fmaxf(rm1, fmaxf(sc[jb][2], sc[jb][3]));
            }
            rm0 = fmaxf(rm0, __shfl_xor_sync(0xffffffffu, rm0, 1));
            rm0 = fmaxf(rm0, __shfl_xor_sync(0xffffffffu, rm0, 2));
            rm1 = fmaxf(rm1, __shfl_xor_sync(0xffffffffu, rm1, 1));
            rm1 = fmaxf(rm1, __shfl_xor_sync(0xffffffffu, rm1, 2));
            const float mx0 = fmaxf(m0, rm0), mx1 = fmaxf(m1, rm1);
            const float corr0 = __expf(m0 - mx0), corr1 = __expf(m1 - mx1);
            float rs0 = 0.f, rs1 = 0.f;
#pragma unroll
            for (int jb = 0; jb < 4; ++jb) {
                sc[jb][0] = __expf(sc[jb][0] - mx0);
                sc[jb][1] = __expf(sc[jb][1] - mx0);
                sc[jb][2] = __expf(sc[jb][2] - mx1);
                sc[jb][3] = __expf(sc[jb][3] - mx1);
                rs0 += sc[jb][0] + sc[jb][1];
                rs1 += sc[jb][2] + sc[jb][3];
            }
            rs0 += __shfl_xor_sync(0xffffffffu, rs0, 1);
            rs0 += __shfl_xor_sync(0xffffffffu, rs0, 2);
            rs1 += __shfl_xor_sync(0xffffffffu, rs1, 1);
            rs1 += __shfl_xor_sync(0xffffffffu, rs1, 2);
            l0 = l0 * corr0 + rs0;  m0 = mx0;
            l1 = l1 * corr1 + rs1;  m1 = mx1;
#pragma unroll
            for (int nb = 0; nb < 16; ++nb) {
                o[nb][0] *= corr0; o[nb][1] *= corr0;
                o[nb][2] *= corr1; o[nb][3] *= corr1;
            }

            // ---- O += P @ V  (P frags straight from S c-frags, no shuffles)
#pragma unroll
            for (int kc = 0; kc < 2; ++kc) {
                uint32_t pa[4];
                pa[0] = packh2(sc[2*kc][0],   sc[2*kc][1]);
                pa[1] = packh2(sc[2*kc][2],   sc[2*kc][3]);
                pa[2] = packh2(sc[2*kc+1][0], sc[2*kc+1][1]);
                pa[3] = packh2(sc[2*kc+1][2], sc[2*kc+1][3]);
#pragma unroll
                for (int cp = 0; cp < 8; ++cp) {
                    uint32_t vf[4];
                    const int row = kc * 16 + l15;
                    const int ch = (cp << 1) + lh;
                    LDSM4T(vf, Vst + row * 256 + ((ch ^ (row & 7)) << 4));
                    mma_h(o[2*cp],   pa, vf[0], vf[1]);
                    mma_h(o[2*cp+1], pa, vf[2], vf[3]);
                }
            }
        }
    }
#undef A_LOAD

    // ---- write O (fp16) ----
    const float inv0 = 1.f / l0, inv1 = 1.f / l1;
    __half* o_r0 = O + base + (size_t)r0 * DMODEL;
    __half* o_r1 = O + base + (size_t)r1 * DMODEL;
#pragma unroll
    for (int nb = 0; nb < 16; ++nb) {
        const int c = nb * 8 + tg * 2;
        *(uint32_t*)&o_r0[c] = packh2(o[nb][0] * inv0, o[nb][1] * inv0);
        *(uint32_t*)&o_r1[c] = packh2(o[nb][2] * inv1, o[nb][3] * inv1);
    }
}

// ---------------- launcher --------------------------------------------------
extern "C" void kernel_launch(void* const* d_in, const int* in_sizes, int n_in,
                              void* d_out, int out_size)
{
    const float* x0      = (const float*)d_in[0];
    const float* x1      = (const float*)d_in[1];
    const float* x2      = (const float*)d_in[2];
    const float* x3      = (const float*)d_in[3];
    const float* freqs   = (const float*)d_in[5];
    const float* wq_w    = (const float*)d_in[7];
    const float* wq_b    = (const float*)d_in[8];
    const float* wk_w    = (const float*)d_in[9];
    const float* wk_b    = (const float*)d_in[10];
    const float* wv_w    = (const float*)d_in[11];
    const float* wv_b    = (const float*)d_in[12];
    const float* wo_w    = (const float*)d_in[13];
    const float* wo_b    = (const float*)d_in[14];
    const float* qn_w    = (const float*)d_in[15];
    const float* kn_w    = (const float*)d_in[16];
    const float* ln0_w   = (const float*)d_in[17];
    const float* ln0_b   = (const float*)d_in[18];
    const float* ln1_w   = (const float*)d_in[19];
    const float* ln1_b   = (const float*)d_in[20];
    const float* ln2_w   = (const float*)d_in[21];
    const float* ln2_b   = (const float*)d_in[22];
    const float* ffn_w   = (const float*)d_in[23];
    const float* ffn_b   = (const float*)d_in[24];
    const float* w1_w    = (const float*)d_in[25];
    const float* w1_b    = (const float*)d_in[26];
    const float* w2_w    = (const float*)d_in[27];
    const float* w2_b    = (const float*)d_in[28];
    float* out = (float*)d_out;

    __half* hs = nullptr;
    float* hbuf = nullptr;
    cudaGetSymbolAddress((void**)&hs, g_h);
    cudaGetSymbolAddress((void**)&hbuf, g_fbuf);
    __half* nq   = hs;               // 3*CH: nq, nk, nv contiguous
    __half* fx   = hs + 3 * CH;
    __half* q    = hs + 4 * CH;
    __half* k    = hs + 5 * CH;
    __half* v    = hs + 6 * CH;
    __half* y    = hs + 7 * CH;
    __half* ffn1 = hs + 8 * CH;
    __half* wq_r = ffn1 + (size_t)TOK * HID;
    __half* wk_r = wq_r + WQKVO_SZ;
    __half* wv_r = wk_r + WQKVO_SZ;
    __half* wo_r = wv_r + WQKVO_SZ;
    __half* w1_r = wo_r + WQKVO_SZ;
    __half* w2_r = w1_r + W12_SZ;
    (void)v;

    cudaFuncSetAttribute(gemm_h_kernel<ACT_NONE, false, true>,
                         cudaFuncAttributeMaxDynamicSharedMemorySize, GSMEM);
    cudaFuncSetAttribute(gemm_h_kernel<ACT_NONE, true, false>,
                         cudaFuncAttributeMaxDynamicSharedMemorySize, GSMEM);
    cudaFuncSetAttribute(gemm_h_kernel<ACT_GELU, false, true>,
                         cudaFuncAttributeMaxDynamicSharedMemorySize, GSMEM);
    cudaFuncSetAttribute(attn_h_kernel,
                         cudaFuncAttributeMaxDynamicSharedMemorySize, ASMEM);

    // 0. convert weights to fp16
    const int nw4 = (int)(WQKVO_SZ / 4), nh4 = (int)(W12_SZ / 4);
    round_h_kernel<<<(nw4 + 255) / 256, 256>>>((const float4*)wq_w, (uint2*)wq_r, nw4);
    round_h_kernel<<<(nw4 + 255) / 256, 256>>>((const float4*)wk_w, (uint2*)wk_r, nw4);
    round_h_kernel<<<(nw4 + 255) / 256, 256>>>((const float4*)wv_w, (uint2*)wv_r, nw4);
    round_h_kernel<<<(nw4 + 255) / 256, 256>>>((const float4*)wo_w, (uint2*)wo_r, nw4);
    round_h_kernel<<<(nh4 + 255) / 256, 256>>>((const float4*)w1_w, (uint2*)w1_r, nh4);
    round_h_kernel<<<(nh4 + 255) / 256, 256>>>((const float4*)w2_w, (uint2*)w2_r, nh4);

    // 1. layernorms (fp16 out; nq,nk,nv contiguous)
    layernorm_kernel<<<TOK, 256>>>(x0, ln0_w, ln0_b, nq);
    layernorm_kernel<<<TOK, 256>>>(x1, ln1_w, ln1_b, nq + CH);
    layernorm_kernel<<<TOK, 256>>>(x2, ln2_w, ln2_b, nq + 2 * CH);
    layernorm_kernel<<<TOK, 256>>>(x3, ffn_w, ffn_b, fx);

    // 2. fused QKV projection
    dim3 gqkv(DMODEL / 256, TOK / 128, 3);
    gemm_h_kernel<ACT_NONE, false, true><<<gqkv, 256, GSMEM>>>(
        nq, wq_r, wq_b, wk_b, wv_b, nullptr, q,
        TOK, DMODEL, DMODEL, CH, WQKVO_SZ, CH);

    // 3. qk rmsnorm + rope (fused q/k via blockIdx.y)
    qknorm_rope_kernel<<<dim3(TOK, 2), 256>>>(q, k, qn_w, kn_w, freqs);

    // 4. causal attention
    attn_h_kernel<<<dim3(SEQ / 64, BATCH * NHEAD), 128, ASMEM>>>(q, k, hs + 6 * CH, y);

    // 5. o-projection + residual (fp32 out)
    dim3 go(DMODEL / 256, TOK / 128, 1);
    gemm_h_kernel<ACT_NONE, true, false><<<go, 256, GSMEM>>>(
        y, wo_r, wo_b, nullptr, nullptr, x3, hbuf,
        TOK, DMODEL, DMODEL, 0, 0, 0);

    // 6. ffn1 + gelu (fp16 out)
    dim3 g1(HID / 256, TOK / 128, 1);
    gemm_h_kernel<ACT_GELU, false, true><<<g1, 256, GSMEM>>>(
        fx, w1_r, w1_b, nullptr, nullptr, nullptr, ffn1,
        TOK, HID, DMODEL, 0, 0, 0);

    // 7. ffn2 + residual -> final fp32 output
    gemm_h_kernel<ACT_NONE, true, false><<<go, 256, GSMEM>>>(
        ffn1, w2_r, w2_b, nullptr, nullptr, hbuf, out,
        TOK, DMODEL, HID, 0, 0, 0);
}

// round 6
// speedup vs baseline: 7.8832x; 1.0404x over previous
#include <cuda_runtime.h>
#include <cuda_fp16.h>
#include <stdint.h>

#define BATCH 2
#define SEQ   2048
#define DMODEL 2048
#define NHEAD 16
#define HDIM  128
#define HID   5888
#define TOK   (BATCH*SEQ)            // 4096
#define CH    ((size_t)TOK*DMODEL)   // 8388608
#define EPSV  1e-5f
#define SCALE_ATT 0.08838834764831845f

#define WQKVO_SZ ((size_t)DMODEL*DMODEL)
#define W12_SZ   ((size_t)HID*DMODEL)
#define HTOT (8*CH + (size_t)TOK*HID + 4*WQKVO_SZ + 2*W12_SZ)

__device__ __half g_h[HTOT];     // half scratch: activations + converted weights
__device__ float g_fbuf[CH];     // fp32 residual buffer (hbuf)

// ---------------- helpers ---------------------------------------------------
__device__ __forceinline__ uint32_t smem_u32(const void* p) {
    uint32_t a;
    asm("{ .reg .u64 t; cvta.to.shared.u64 t, %1; cvt.u32.u64 %0, t; }"
        : "=r"(a) : "l"(p));
    return a;
}
__device__ __forceinline__ uint32_t packh2(float a, float b) {
    __half2 h = __floats2half2_rn(a, b);
    return *(uint32_t*)&h;
}
__device__ __forceinline__ void cpasync16(uint32_t dst, const void* src) {
    asm volatile("cp.async.cg.shared.global [%0], [%1], 16;" :: "r"(dst), "l"(src) : "memory");
}
#define CP_COMMIT() asm volatile("cp.async.commit_group;" ::: "memory")
#define CP_WAIT2()  asm volatile("cp.async.wait_group 2;" ::: "memory")

#define LDSM4(r, addr) \
    asm volatile("ldmatrix.sync.aligned.m8n8.x4.shared.b16 {%0,%1,%2,%3}, [%4];" \
        : "=r"((r)[0]), "=r"((r)[1]), "=r"((r)[2]), "=r"((r)[3]) : "r"(addr))
#define LDSM4T(r, addr) \
    asm volatile("ldmatrix.sync.aligned.m8n8.x4.trans.shared.b16 {%0,%1,%2,%3}, [%4];" \
        : "=r"((r)[0]), "=r"((r)[1]), "=r"((r)[2]), "=r"((r)[3]) : "r"(addr))

__device__ __forceinline__ void mma_h(float (&c)[4], const uint32_t (&a)[4],
                                      uint32_t b0, uint32_t b1) {
    asm volatile(
        "mma.sync.aligned.m16n8k16.row.col.f32.f16.f16.f32 "
        "{%0,%1,%2,%3}, {%4,%5,%6,%7}, {%8,%9}, {%0,%1,%2,%3};\n"
        : "+f"(c[0]), "+f"(c[1]), "+f"(c[2]), "+f"(c[3])
        : "r"(a[0]), "r"(a[1]), "r"(a[2]), "r"(a[3]), "r"(b0), "r"(b1));
}

// ---------------- fused fp32 -> fp16 weight conversion (6 tensors) ----------
__global__ __launch_bounds__(256) void round_h6_kernel(
    const float4* __restrict__ s0, const float4* __restrict__ s1,
    const float4* __restrict__ s2, const float4* __restrict__ s3,
    const float4* __restrict__ s4, const float4* __restrict__ s5,
    uint2* __restrict__ d0, uint2* __restrict__ d1,
    uint2* __restrict__ d2, uint2* __restrict__ d3,
    uint2* __restrict__ d4, uint2* __restrict__ d5,
    int nw4, int nh4)
{
    const int z = blockIdx.y;
    const int n4 = (z < 4) ? nw4 : nh4;
    const int i = blockIdx.x * 256 + threadIdx.x;
    if (i >= n4) return;
    const float4* in = (z == 0) ? s0 : (z == 1) ? s1 : (z == 2) ? s2
                     : (z == 3) ? s3 : (z == 4) ? s4 : s5;
    uint2* out = (z == 0) ? d0 : (z == 1) ? d1 : (z == 2) ? d2
               : (z == 3) ? d3 : (z == 4) ? d4 : d5;
    float4 v = in[i];
    uint2 u;
    u.x = packh2(v.x, v.y);
    u.y = packh2(v.z, v.w);
    out[i] = u;
}

// ---------------- fused layernorm x4 (fp32 in, fp16 out) --------------------
__global__ __launch_bounds__(256) void layernorm4_kernel(
    const float* __restrict__ x0, const float* __restrict__ x1,
    const float* __restrict__ x2, const float* __restrict__ x3,
    const float* __restrict__ w0, const float* __restrict__ w1,
    const float* __restrict__ w2, const float* __restrict__ w3,
    const float* __restrict__ b0p, const float* __restrict__ b1p,
    const float* __restrict__ b2p, const float* __restrict__ b3p,
    __half* __restrict__ o0p, __half* __restrict__ o1p,
    __half* __restrict__ o2p, __half* __restrict__ o3p)
{
    const int z = blockIdx.y;
    const float* x = (z == 0) ? x0 : (z == 1) ? x1 : (z == 2) ? x2 : x3;
    const float* w = (z == 0) ? w0 : (z == 1) ? w1 : (z == 2) ? w2 : w3;
    const float* b = (z == 0) ? b0p : (z == 1) ? b1p : (z == 2) ? b2p : b3p;
    __half* out    = (z == 0) ? o0p : (z == 1) ? o1p : (z == 2) ? o2p : o3p;

    const int row = blockIdx.x;
    const int t = threadIdx.x;
    const float4* xp = (const float4*)(x + (size_t)row * DMODEL);
    float4 v0 = xp[t], v1 = xp[t + 256];
    float s  = v0.x + v0.y + v0.z + v0.w + v1.x + v1.y + v1.z + v1.w;
    float ss = v0.x*v0.x + v0.y*v0.y + v0.z*v0.z + v0.w*v0.w
             + v1.x*v1.x + v1.y*v1.y + v1.z*v1.z + v1.w*v1.w;
    __shared__ float sred[16];
    const int lane = t & 31, warp = t >> 5;
#pragma unroll
    for (int o = 16; o; o >>= 1) {
        s  += __shfl_xor_sync(0xffffffffu, s,  o);
        ss += __shfl_xor_sync(0xffffffffu, ss, o);
    }
    if (lane == 0) { sred[warp] = s; sred[8 + warp] = ss; }
    __syncthreads();
    if (t < 32) {
        s  = (t < 8) ? sred[t]     : 0.f;
        ss = (t < 8) ? sred[8 + t] : 0.f;
#pragma unroll
        for (int o = 4; o; o >>= 1) {
            s  += __shfl_xor_sync(0xffffffffu, s,  o);
            ss += __shfl_xor_sync(0xffffffffu, ss, o);
        }
        if (t == 0) { sred[0] = s; sred[1] = ss; }
    }
    __syncthreads();
    const float mean = sred[0] * (1.f / DMODEL);
    const float var  = sred[1] * (1.f / DMODEL) - mean * mean;
    const float inv  = rsqrtf(var + EPSV);
    const float4* wp = (const float4*)w;
    const float4* bp = (const float4*)b;
    float4 wv0 = wp[t], wv1 = wp[t + 256], bv0 = bp[t], bv1 = bp[t + 256];
    uint2 u0, u1;
    u0.x = packh2((v0.x - mean) * inv * wv0.x + bv0.x, (v0.y - mean) * inv * wv0.y + bv0.y);
    u0.y = packh2((v0.z - mean) * inv * wv0.z + bv0.z, (v0.w - mean) * inv * wv0.w + bv0.w);
    u1.x = packh2((v1.x - mean) * inv * wv1.x + bv1.x, (v1.y - mean) * inv * wv1.y + bv1.y);
    u1.y = packh2((v1.z - mean) * inv * wv1.z + bv1.z, (v1.w - mean) * inv * wv1.w + bv1.w);
    uint2* op = (uint2*)(out + (size_t)row * DMODEL);
    op[t] = u0;
    op[t + 256] = u1;
}

// ------- pipelined fp16 mma GEMM: C[M,N] = A[M,K] @ Bw[N,K]^T ---------------
// 128(M) x 256(N) CTA tile, BK=64 halves (128B rows), 4 stages, 8 warps 64x64.
#define ACT_NONE 0
#define ACT_GELU 1
#define GSTAGE 49152            // A 16KB + B 32KB
#define GSMEM  (4 * GSTAGE)     // 192 KB

template <int ACT, bool RES, bool OUTH>
__global__ __launch_bounds__(256, 1) void gemm_h_kernel(
    const __half* __restrict__ A, const __half* __restrict__ Bw,
    const float* __restrict__ bias0, const float* __restrict__ bias1,
    const float* __restrict__ bias2, const float* __restrict__ Resid,
    void* __restrict__ Cv, int M, int N, int K,
    size_t aZ, size_t wZ, size_t cZ)
{
    extern __shared__ char smem[];
    const uint32_t s0 = smem_u32(smem);
    const int tid = threadIdx.x;
    const int warp = tid >> 5, lane = tid & 31;
    const int wm = (warp & 1) << 6;
    const int wn = (warp >> 1) << 6;
    const int l15 = lane & 15, lh = lane >> 4;
    const int z = blockIdx.z;
    const float* bias = (z == 0) ? bias0 : (z == 1) ? bias1 : bias2;
    const __half* Ab = A  + (size_t)z * aZ + (size_t)(blockIdx.y * 128) * K;
    const __half* Bb = Bw + (size_t)z * wZ + (size_t)(blockIdx.x * 256) * K;
    const int nk = K >> 6;

#define G_LOAD(kt)                                                            \
    {                                                                         \
        const int st_ = (kt) & 3;                                             \
        const uint32_t sA_ = s0 + st_ * GSTAGE;                               \
        const uint32_t sB_ = sA_ + 16384;                                     \
        const size_t kof_ = (size_t)(kt) * 64;                                \
        _Pragma("unroll")                                                     \
        for (int p = 0; p < 4; ++p) {                                         \
            const int cid = tid + (p << 8);                                   \
            const int row = cid >> 3, c4 = cid & 7;                           \
            const uint32_t sw = row * 128 + ((c4 ^ (row & 7)) << 4);          \
            cpasync16(sA_ + sw, Ab + (size_t)row * K + kof_ + c4 * 8);        \
        }                                                                     \
        _Pragma("unroll")                                                     \
        for (int p = 0; p < 8; ++p) {                                         \
            const int cid = tid + (p << 8);                                   \
            const int row = cid >> 3, c4 = cid & 7;                           \
            const uint32_t sw = row * 128 + ((c4 ^ (row & 7)) << 4);          \
            cpasync16(sB_ + sw, Bb + (size_t)row * K + kof_ + c4 * 8);        \
        }                                                                     \
    }

    G_LOAD(0); CP_COMMIT();
    G_LOAD(1); CP_COMMIT();
    G_LOAD(2); CP_COMMIT();

    float acc[4][8][4];
#pragma unroll
    for (int i = 0; i < 4; i++)
#pragma unroll
        for (int j = 0; j < 8; j++)
#pragma unroll
            for (int r = 0; r < 4; r++) acc[i][j][r] = 0.f;

    for (int kt = 0; kt < nk; ++kt) {
        CP_WAIT2();
        __syncthreads();
        if (kt + 3 < nk) G_LOAD(kt + 3);
        CP_COMMIT();

        const uint32_t sA = s0 + (kt & 3) * GSTAGE, sB = sA + 16384;
#pragma unroll
        for (int kk = 0; kk < 4; ++kk) {
            uint32_t af[4][4], bf[4][4];
            const int ch = (kk << 1) + lh;
#pragma unroll
            for (int i = 0; i < 4; ++i) {
                const int row = wm + i * 16 + l15;
                LDSM4(af[i], sA + row * 128 + ((ch ^ (row & 7)) << 4));
            }
#pragma unroll
            for (int jp = 0; jp < 4; ++jp) {
                const int row = wn + jp * 16 + l15;
                LDSM4(bf[jp], sB + row * 128 + ((ch ^ (row & 7)) << 4));
            }
#pragma unroll
            for (int i = 0; i < 4; ++i)
#pragma unroll
                for (int jp = 0; jp < 4; ++jp) {
                    mma_h(acc[i][2*jp],   af[i], bf[jp][0], bf[jp][2]);
                    mma_h(acc[i][2*jp+1], af[i], bf[jp][1], bf[jp][3]);
                }
        }
    }
#undef G_LOAD

    // epilogue
    const int g = lane >> 2, tg = lane & 3;
    const int rowbase = blockIdx.y * 128 + wm;
    const int colbase = blockIdx.x * 256 + wn;
#pragma unroll
    for (int i = 0; i < 4; ++i) {
#pragma unroll
        for (int j = 0; j < 8; ++j) {
            const int r0 = rowbase + i * 16 + g;
            const int c0 = colbase + j * 8 + tg * 2;
            const float bia0 = bias[c0], bia1 = bias[c0 + 1];
#pragma unroll
            for (int hr = 0; hr < 2; ++hr) {
                const int row = r0 + hr * 8;
                float v0 = acc[i][j][hr * 2 + 0] + bia0;
                float v1 = acc[i][j][hr * 2 + 1] + bia1;
                if (RES) {
                    v0 += Resid[(size_t)row * N + c0];
                    v1 += Resid[(size_t)row * N + c0 + 1];
                }
                if (ACT == ACT_GELU) {
                    v0 = 0.5f * v0 * (1.f + erff(v0 * 0.7071067811865475f));
                    v1 = 0.5f * v1 * (1.f + erff(v1 * 0.7071067811865475f));
                }
                if (OUTH) {
                    __half* Cb = (__half*)Cv + (size_t)z * cZ;
                    *(uint32_t*)&Cb[(size_t)row * N + c0] = packh2(v0, v1);
                } else {
                    float* Cb = (float*)Cv + (size_t)z * cZ;
                    *(float2*)&Cb[(size_t)row * N + c0] = make_float2(v0, v1);
                }
            }
        }
    }
}

// ---------------- per-head rmsnorm + rope (fp16 in-place) -------------------
__global__ __launch_bounds__(256) void qknorm_rope_kernel(
    __half* __restrict__ q, __half* __restrict__ k,
    const float* __restrict__ qn, const float* __restrict__ kn,
    const float* __restrict__ freqs)
{
    const int token = blockIdx.x;
    __half* x = blockIdx.y ? k : q;
    const float* w = blockIdx.y ? kn : qn;
    const int pos = token & (SEQ - 1);
    const int warp = threadIdx.x >> 5, lane = threadIdx.x & 31;
    __shared__ float rb[8][32];
    const float4 wv = ((const float4*)w)[lane];
#pragma unroll
    for (int hh = 0; hh < 2; hh++) {
        const int h = warp + hh * 8;
        __half* p = x + (size_t)token * DMODEL + h * HDIM;
        uint2 raw = ((uint2*)p)[lane];
        const __half2 h0 = *(__half2*)&raw.x, h1 = *(__half2*)&raw.y;
        float v0 = __low2float(h0), v1 = __high2float(h0);
        float v2 = __low2float(h1), v3 = __high2float(h1);
        float ssq = v0*v0 + v1*v1 + v2*v2 + v3*v3;
#pragma unroll
        for (int o = 16; o; o >>= 1) ssq += __shfl_xor_sync(0xffffffffu, ssq, o);
        const float inv = rsqrtf(ssq * (1.f / HDIM) + EPSV);
        float o0 = v0 * inv * wv.x, o1 = v1 * inv * wv.y;
        float o2 = v2 * inv * wv.z, o3 = v3 * inv * wv.w;
        const int d0 = lane * 4;
        if (d0 < 32) {
            rb[warp][d0] = o0; rb[warp][d0 + 1] = o1;
            rb[warp][d0 + 2] = o2; rb[warp][d0 + 3] = o3;
        }
        __syncwarp();
        if (d0 < 32) {
            float r[4];
#pragma unroll
            for (int i = 0; i < 4; i++) {
                const int d = d0 + i, ii = d >> 1;
                const float x1 = rb[warp][ii], x2 = rb[warp][ii + 16];
                const float c  = freqs[pos * 32 + ii * 2];
                const float sn = freqs[pos * 32 + ii * 2 + 1];
                r[i] = (d & 1) ? (x2 * c + x1 * sn) : (x1 * c - x2 * sn);
            }
            o0 = r[0]; o1 = r[1]; o2 = r[2]; o3 = r[3];
        }
        __syncwarp();
        raw.x = packh2(o0, o1);
        raw.y = packh2(o2, o3);
        ((uint2*)p)[lane] = raw;
    }
}

// ---------------- causal flash attention (fp16 mma) -------------------------
// 64 q-rows/CTA, 4 warps (16 rows each), kv tiles of 32, 4-stage cp.async.
#define ASTAGE 16384            // K 8KB + V 8KB
#define ASMEM  (4 * ASTAGE)     // 64 KB

__global__ __launch_bounds__(128, 3) void attn_h_kernel(
    const __half* __restrict__ Q, const __half* __restrict__ Kx,
    const __half* __restrict__ Vx, __half* __restrict__ O)
{
    extern __shared__ char smem[];
    const uint32_t s0 = smem_u32(smem);
    const int tid = threadIdx.x;
    const int warp = tid >> 5, lane = tid & 31;
    const int g = lane >> 2, tg = lane & 3;
    const int l15 = lane & 15, lh = lane >> 4;
    const int qb = blockIdx.x, bh = blockIdx.y;
    const int b = bh >> 4, h = bh & 15;
    const size_t base = ((size_t)b * SEQ) * DMODEL + h * HDIM;
    const int q0 = qb * 64;
    const int wq = warp * 16;
    const int nkt = (q0 >> 5) + 2;
    const int r0 = q0 + wq + g, r1 = r0 + 8;

    // Q fragments: 8 k16-chunks over d=128
    uint32_t aq[8][4];
    {
        const __half* q_r0 = Q + base + (size_t)r0 * DMODEL;
        const __half* q_r1 = q_r0 + (size_t)8 * DMODEL;
#pragma unroll
        for (int kk = 0; kk < 8; ++kk) {
            aq[kk][0] = *(const uint32_t*)(q_r0 + kk * 16 + tg * 2);
            aq[kk][1] = *(const uint32_t*)(q_r1 + kk * 16 + tg * 2);
            aq[kk][2] = *(const uint32_t*)(q_r0 + kk * 16 + 8 + tg * 2);
            aq[kk][3] = *(const uint32_t*)(q_r1 + kk * 16 + 8 + tg * 2);
        }
    }

#define A_LOAD(kt)                                                            \
    {                                                                         \
        const int st_ = (kt) & 3;                                             \
        const uint32_t Kst_ = s0 + st_ * ASTAGE;                              \
        const uint32_t Vst_ = Kst_ + 8192;                                    \
        const int kv0_ = (kt) << 5;                                           \
        _Pragma("unroll")                                                     \
        for (int p = 0; p < 4; ++p) {                                         \
            const int cid = tid + (p << 7);                                   \
            const int row = cid >> 4, c = cid & 15;                           \
            const uint32_t sw = row * 256 + ((c ^ (row & 7)) << 4);           \
            const size_t go = base + (size_t)(kv0_ + row) * DMODEL + c * 8;   \
            cpasync16(Kst_ + sw, Kx + go);                                    \
            cpasync16(Vst_ + sw, Vx + go);                                    \
        }                                                                     \
    }

    A_LOAD(0); CP_COMMIT();
    A_LOAD(1); CP_COMMIT();
    A_LOAD(2); CP_COMMIT();

    float m0 = -1e30f, m1 = -1e30f, l0 = 0.f, l1 = 0.f;
    float o[16][4];
#pragma unroll
    for (int nb = 0; nb < 16; ++nb)
#pragma unroll
        for (int r = 0; r < 4; ++r) o[nb][r] = 0.f;

    for (int kt = 0; kt < nkt; ++kt) {
        CP_WAIT2();
        __syncthreads();
        if (kt + 3 < nkt) A_LOAD(kt + 3);
        CP_COMMIT();

        const int kv0 = kt << 5;
        if (kv0 <= q0 + wq + 15) {
            const uint32_t Kst = s0 + (kt & 3) * ASTAGE;
            const uint32_t Vst = Kst + 8192;

            // ---- S = Q @ K^T ----
            float sc[4][4];
#pragma unroll
            for (int jb = 0; jb < 4; ++jb)
#pragma unroll
                for (int r = 0; r < 4; ++r) sc[jb][r] = 0.f;
#pragma unroll
            for (int kk = 0; kk < 8; ++kk) {
                const int ch = (kk << 1) + lh;
#pragma unroll
                for (int jp = 0; jp < 2; ++jp) {
                    uint32_t bf[4];
                    const int row = jp * 16 + l15;
                    LDSM4(bf, Kst + row * 256 + ((ch ^ (row & 7)) << 4));
                    mma_h(sc[2*jp],   aq[kk], bf[0], bf[2]);
                    mma_h(sc[2*jp+1], aq[kk], bf[1], bf[3]);
                }
            }

            // ---- scale + causal mask ----
            const bool diag = (kv0 + 31 > r0) || (kv0 + 31 > r1);
#pragma unroll
            for (int jb = 0; jb < 4; ++jb) {
                const int c0 = kv0 + jb * 8 + tg * 2;
                sc[jb][0] *= SCALE_ATT; sc[jb][1] *= SCALE_ATT;
                sc[jb][2] *= SCALE_ATT; sc[jb][3] *= SCALE_ATT;
                if (diag) {
                    if (c0     > r0) sc[jb][0] = -1e30f;
                    if (c0 + 1 > r0) sc[jb][1] = -1e30f;
                    if (c0     > r1) sc[jb][2] = -1e30f;
                    if (c0 + 1 > r1) sc[jb][3] = -1e30f;
                }
            }

            // ---- online softmax ----
            float rm0 = sc[0][0], rm1 = sc[0][2];
#pragma unroll
            for (int jb = 0; jb < 4; ++jb) {
                rm0 = fmaxf(rm0, fmaxf(sc[jb][0], sc[jb][1]));
                rm1 = fmaxf(rm1, fmaxf(sc[jb][2], sc[jb][3]));
            }
            rm0 = fmaxf(rm0, __shfl_xor_sync(0xffffffffu, rm0, 1));
            rm0 = fmaxf(rm0, __shfl_xor_sync(0xffffffffu, rm0, 2));
            rm1 = fmaxf(rm1, __shfl_xor_sync(0xffffffffu, rm1, 1));
            rm1 = fmaxf(rm1, __shfl_xor_sync(0xffffffffu, rm1, 2));
            const float mx0 = fmaxf(m0, rm0), mx1 = fmaxf(m1, rm1);
            const float corr0 = __expf(m0 - mx0), corr1 = __expf(m1 - mx1);
            float rs0 = 0.f, rs1 = 0.f;
#pragma unroll
            for (int jb = 0; jb < 4; ++jb) {
                sc[jb][0] = __expf(sc[jb][0] - mx0);
                sc[jb][1] = __expf(sc[jb][1] - mx0);
                sc[jb][2] = __expf(sc[jb][2] - mx1);
                sc[jb][3] = __expf(sc[jb][3] - mx1);
                rs0 += sc[jb][0] + sc[jb][1];
                rs1 += sc[jb][2] + sc[jb][3];
            }
            rs0 += __shfl_xor_sync(0xffffffffu, rs0, 1);
            rs0 += __shfl_xor_sync(0xffffffffu, rs0, 2);
            rs1 += __shfl_xor_sync(0xffffffffu, rs1, 1);
            rs1 += __shfl_xor_sync(0xffffffffu, rs1, 2);
            l0 = l0 * corr0 + rs0;  m0 = mx0;
            l1 = l1 * corr1 + rs1;  m1 = mx1;
#pragma unroll
            for (int nb = 0; nb < 16; ++nb) {
                o[nb][0] *= corr0; o[nb][1] *= corr0;
                o[nb][2] *= corr1; o[nb][3] *= corr1;
            }

            // ---- O += P @ V  (P frags straight from S c-frags) ----
#pragma unroll
            for (int kc = 0; kc < 2; ++kc) {
                uint32_t pa[4];
                pa[0] = packh2(sc[2*kc][0],   sc[2*kc][1]);
                pa[1] = packh2(sc[2*kc][2],   sc[2*kc][3]);
                pa[2] = packh2(sc[2*kc+1][0], sc[2*kc+1][1]);
                pa[3] = packh2(sc[2*kc+1][2], sc[2*kc+1][3]);
#pragma unroll
                for (int cp = 0; cp < 8; ++cp) {
                    uint32_t vf[4];
                    const int row = kc * 16 + l15;
                    const int ch = (cp << 1) + lh;
                    LDSM4T(vf, Vst + row * 256 + ((ch ^ (row & 7)) << 4));
                    mma_h(o[2*cp],   pa, vf[0], vf[1]);
                    mma_h(o[2*cp+1], pa, vf[2], vf[3]);
                }
            }
        }
    }
#undef A_LOAD

    // ---- write O (fp16) ----
    const float inv0 = 1.f / l0, inv1 = 1.f / l1;
    __half* o_r0 = O + base + (size_t)r0 * DMODEL;
    __half* o_r1 = O + base + (size_t)r1 * DMODEL;
#pragma unroll
    for (int nb = 0; nb < 16; ++nb) {
        const int c = nb * 8 + tg * 2;
        *(uint32_t*)&o_r0[c] = packh2(o[nb][0] * inv0, o[nb][1] * inv0);
        *(uint32_t*)&o_r1[c] = packh2(o[nb][2] * inv1, o[nb][3] * inv1);
    }
}

// ---------------- launcher --------------------------------------------------
static cudaStream_t g_side = nullptr;
static cudaEvent_t g_evf = nullptr, g_evj = nullptr;

extern "C" void kernel_launch(void* const* d_in, const int* in_sizes, int n_in,
                              void* d_out, int out_size)
{
    const float* x0      = (const float*)d_in[0];
    const float* x1      = (const float*)d_in[1];
    const float* x2      = (const float*)d_in[2];
    const float* x3      = (const float*)d_in[3];
    const float* freqs   = (const float*)d_in[5];
    const float* wq_w    = (const float*)d_in[7];
    const float* wq_b    = (const float*)d_in[8];
    const float* wk_w    = (const float*)d_in[9];
    const float* wk_b    = (const float*)d_in[10];
    const float* wv_w    = (const float*)d_in[11];
    const float* wv_b    = (const float*)d_in[12];
    const float* wo_w    = (const float*)d_in[13];
    const float* wo_b    = (const float*)d_in[14];
    const float* qn_w    = (const float*)d_in[15];
    const float* kn_w    = (const float*)d_in[16];
    const float* ln0_w   = (const float*)d_in[17];
    const float* ln0_b   = (const float*)d_in[18];
    const float* ln1_w   = (const float*)d_in[19];
    const float* ln1_b   = (const float*)d_in[20];
    const float* ln2_w   = (const float*)d_in[21];
    const float* ln2_b   = (const float*)d_in[22];
    const float* ffn_w   = (const float*)d_in[23];
    const float* ffn_b   = (const float*)d_in[24];
    const float* w1_w    = (const float*)d_in[25];
    const float* w1_b    = (const float*)d_in[26];
    const float* w2_w    = (const float*)d_in[27];
    const float* w2_b    = (const float*)d_in[28];
    float* out = (float*)d_out;

    __half* hs = nullptr;
    float* hbuf = nullptr;
    cudaGetSymbolAddress((void**)&hs, g_h);
    cudaGetSymbolAddress((void**)&hbuf, g_fbuf);
    __half* nq   = hs;               // nq, nk, nv contiguous
    __half* fx   = hs + 3 * CH;
    __half* q    = hs + 4 * CH;
    __half* k    = hs + 5 * CH;
    __half* v    = hs + 6 * CH;
    __half* y    = hs + 7 * CH;
    __half* ffn1 = hs + 8 * CH;
    __half* wq_r = ffn1 + (size_t)TOK * HID;
    __half* wk_r = wq_r + WQKVO_SZ;
    __half* wv_r = wk_r + WQKVO_SZ;
    __half* wo_r = wv_r + WQKVO_SZ;
    __half* w1_r = wo_r + WQKVO_SZ;
    __half* w2_r = w1_r + W12_SZ;

    if (!g_side) {
        cudaStreamCreateWithFlags(&g_side, cudaStreamNonBlocking);
        cudaEventCreateWithFlags(&g_evf, cudaEventDisableTiming);
        cudaEventCreateWithFlags(&g_evj, cudaEventDisableTiming);
    }

    cudaFuncSetAttribute(gemm_h_kernel<ACT_NONE, false, true>,
                         cudaFuncAttributeMaxDynamicSharedMemorySize, GSMEM);
    cudaFuncSetAttribute(gemm_h_kernel<ACT_NONE, true, false>,
                         cudaFuncAttributeMaxDynamicSharedMemorySize, GSMEM);
    cudaFuncSetAttribute(gemm_h_kernel<ACT_GELU, false, true>,
                         cudaFuncAttributeMaxDynamicSharedMemorySize, GSMEM);
    cudaFuncSetAttribute(attn_h_kernel,
                         cudaFuncAttributeMaxDynamicSharedMemorySize, ASMEM);

    // 0. convert all 6 weight tensors to fp16 (one fused launch)
    const int nw4 = (int)(WQKVO_SZ / 4), nh4 = (int)(W12_SZ / 4);
    round_h6_kernel<<<dim3((nh4 + 255) / 256, 6), 256>>>(
        (const float4*)wq_w, (const float4*)wk_w, (const float4*)wv_w,
        (const float4*)wo_w, (const float4*)w1_w, (const float4*)w2_w,
        (uint2*)wq_r, (uint2*)wk_r, (uint2*)wv_r,
        (uint2*)wo_r, (uint2*)w1_r, (uint2*)w2_r, nw4, nh4);

    // 1. fused layernorms (fp16 out; nq,nk,nv contiguous)
    layernorm4_kernel<<<dim3(TOK, 4), 256>>>(
        x0, x1, x2, x3,
        ln0_w, ln1_w, ln2_w, ffn_w,
        ln0_b, ln1_b, ln2_b, ffn_b,
        nq, nq + CH, nq + 2 * CH, fx);

    // fork: ffn1 runs concurrently with the attention path
    cudaEventRecord(g_evf, 0);
    cudaStreamWaitEvent(g_side, g_evf, 0);
    dim3 g1(HID / 256, TOK / 128, 1);
    gemm_h_kernel<ACT_GELU, false, true><<<g1, 256, GSMEM, g_side>>>(
        fx, w1_r, w1_b, nullptr, nullptr, nullptr, ffn1,
        TOK, HID, DMODEL, 0, 0, 0);
    cudaEventRecord(g_evj, g_side);

    // 2. fused QKV projection (main stream)
    dim3 gqkv(DMODEL / 256, TOK / 128, 3);
    gemm_h_kernel<ACT_NONE, false, true><<<gqkv, 256, GSMEM>>>(
        nq, wq_r, wq_b, wk_b, wv_b, nullptr, q,
        TOK, DMODEL, DMODEL, CH, WQKVO_SZ, CH);

    // 3. qk rmsnorm + rope
    qknorm_rope_kernel<<<dim3(TOK, 2), 256>>>(q, k, qn_w, kn_w, freqs);

    // 4. causal attention
    attn_h_kernel<<<dim3(SEQ / 64, BATCH * NHEAD), 128, ASMEM>>>(q, k, v, y);

    // 5. o-projection + residual (fp32 out)
    dim3 go(DMODEL / 256, TOK / 128, 1);
    gemm_h_kernel<ACT_NONE, true, false><<<go, 256, GSMEM>>>(
        y, wo_r, wo_b, nullptr, nullptr, x3, hbuf,
        TOK, DMODEL, DMODEL, 0, 0, 0);

    // join: ffn2 needs ffn1 + hbuf
    cudaStreamWaitEvent(0, g_evj, 0);

    // 6. ffn2 + residual -> final fp32 output
    gemm_h_kernel<ACT_NONE, true, false><<<go, 256, GSMEM>>>(
        ffn1, w2_r, w2_b, nullptr, nullptr, hbuf, out,
        TOK, DMODEL, HID, 0, 0, 0);
}